// round 2
// baseline (speedup 1.0000x reference)
#include <cuda_runtime.h>

#define MAXN 100000

// ---------------- device scratch (static: no allocations allowed) ----------------
__device__ float  g_bn[8];              // sum[4], sumsq[4]
__device__ float  g_deg[MAXN];
__device__ float4 g_enc_acc[MAXN];      // {mu0,mu1,lv0,lv1} sums
__device__ float4 g_dec_acc[MAXN];      // {o0..o3} sums
__device__ float4 g_ea[MAXN * 8];       // A@xn + b1  (N x 32)
__device__ float4 g_eb[MAXN * 8];       // B@xn       (N x 32)
__device__ float4 g_da[MAXN * 8];       // decoder A@z + b1
__device__ float4 g_db[MAXN * 8];       // decoder B@z

__device__ __forceinline__ void red_add_v4(float* p, float a, float b, float c, float d) {
    asm volatile("red.global.add.v4.f32 [%0], {%1,%2,%3,%4};"
                 :: "l"(p), "f"(a), "f"(b), "f"(c), "f"(d) : "memory");
}

// ---------------- zero accumulators ----------------
__global__ void k_zero(int n) {
    int t = blockIdx.x * blockDim.x + threadIdx.x;
    int stride = gridDim.x * blockDim.x;
    float4 z = make_float4(0.f, 0.f, 0.f, 0.f);
    for (int i = t; i < n; i += stride) {
        g_enc_acc[i] = z;
        g_dec_acc[i] = z;
        g_deg[i] = 0.f;
    }
    if (t < 8) g_bn[t] = 0.f;
}

// ---------------- batchnorm statistics ----------------
__global__ void k_bn_reduce(const float4* __restrict__ x, int n) {
    int t = blockIdx.x * blockDim.x + threadIdx.x;
    int stride = gridDim.x * blockDim.x;
    float s[4] = {0.f, 0.f, 0.f, 0.f};
    float q[4] = {0.f, 0.f, 0.f, 0.f};
    for (int i = t; i < n; i += stride) {
        float4 v = x[i];
        s[0] += v.x; q[0] += v.x * v.x;
        s[1] += v.y; q[1] += v.y * v.y;
        s[2] += v.z; q[2] += v.z * v.z;
        s[3] += v.w; q[3] += v.w * v.w;
    }
#pragma unroll
    for (int o = 16; o > 0; o >>= 1) {
#pragma unroll
        for (int c = 0; c < 4; c++) {
            s[c] += __shfl_down_sync(0xffffffffu, s[c], o);
            q[c] += __shfl_down_sync(0xffffffffu, q[c], o);
        }
    }
    if ((threadIdx.x & 31) == 0) {
#pragma unroll
        for (int c = 0; c < 4; c++) {
            atomicAdd(&g_bn[c], s[c]);
            atomicAdd(&g_bn[4 + c], q[c]);
        }
    }
}

// ---------------- degree counts ----------------
__global__ void k_deg(const int* __restrict__ dst, int E, int n) {
    int t = blockIdx.x * blockDim.x + threadIdx.x;
    int stride = gridDim.x * blockDim.x;
    for (int e = t; e < E; e += stride) {
        unsigned i = (unsigned)dst[e];
        if (i < (unsigned)n) atomicAdd(&g_deg[i], 1.0f);
    }
}

// ---------------- encoder node precompute: BN + linearized layer 1 ----------------
__global__ void k_prep_enc(const float4* __restrict__ x,
                           const float* __restrict__ w1, const float* __restrict__ b1,
                           const float* __restrict__ gamma, const float* __restrict__ beta,
                           int n) {
    __shared__ float sw[256];   // enc_w1 (32 x 8) row-major
    __shared__ float sb1[32];
    __shared__ float sm[4], ss[4], sbt[4];
    int tid = threadIdx.x;
    if (tid < 256) sw[tid] = w1[tid];
    if (tid < 32)  sb1[tid] = b1[tid];
    if (tid < 4) {
        float m = g_bn[tid] / (float)n;
        float var = g_bn[4 + tid] / (float)n - m * m;
        sm[tid]  = m;
        ss[tid]  = rsqrtf(var + 1e-5f) * gamma[tid];
        sbt[tid] = beta[tid];
    }
    __syncthreads();
    int t = blockIdx.x * blockDim.x + tid;
    int stride = gridDim.x * blockDim.x;
    for (int i = t; i < n; i += stride) {
        float4 xv = x[i];
        float x0 = (xv.x - sm[0]) * ss[0] + sbt[0];
        float x1 = (xv.y - sm[1]) * ss[1] + sbt[1];
        float x2 = (xv.z - sm[2]) * ss[2] + sbt[2];
        float x3 = (xv.w - sm[3]) * ss[3] + sbt[3];
        float4 ra[8], rb[8];
        float* pa = (float*)ra;
        float* pb = (float*)rb;
#pragma unroll
        for (int k = 0; k < 32; k++) {
            const float* w = sw + k * 8;
            float b = w[4] * x0 + w[5] * x1 + w[6] * x2 + w[7] * x3;
            float a = sb1[k] + w[0] * x0 + w[1] * x1 + w[2] * x2 + w[3] * x3 - b;
            pa[k] = a;
            pb[k] = b;
        }
#pragma unroll
        for (int q8 = 0; q8 < 8; q8++) {
            g_ea[i * 8 + q8] = ra[q8];
            g_eb[i * 8 + q8] = rb[q8];
        }
    }
}

// ---------------- unified per-edge kernel (PHASE 0 = encoder, 1 = decoder) ----------------
// u = relu(fa[dst] + fb[src]); v = relu(W2 @ u + b2); p = [pA; pB] @ v;  red.v4 -> acc[dst]
template <int PHASE>
__global__ void __launch_bounds__(256)
k_edge(const int* __restrict__ ei, int E, int n,
       const float* __restrict__ w2, const float* __restrict__ b2,
       const float* __restrict__ pA, const float* __restrict__ pB) {
    __shared__ float4 sw2[256];   // 32x32 row-major as float4
    __shared__ float  sb2[32];
    __shared__ float4 spt[32];    // transposed projection: per k {pA0,pA1,pB0,pB1}
    int tid = threadIdx.x;
    sw2[tid] = ((const float4*)w2)[tid];
    if (tid < 32) {
        sb2[tid] = b2[tid];
        spt[tid] = make_float4(pA[tid], pA[32 + tid], pB[tid], pB[32 + tid]);
    }
    __syncthreads();

    const float4* fa = (PHASE == 0) ? g_ea : g_da;
    const float4* fb = (PHASE == 0) ? g_eb : g_db;
    float* acc = (PHASE == 0) ? (float*)g_enc_acc : (float*)g_dec_acc;

    int t = blockIdx.x * blockDim.x + tid;
    int stride = gridDim.x * blockDim.x;
    for (int e = t; e < E; e += stride) {
        unsigned j = (unsigned)ei[e];       // src
        unsigned i = (unsigned)ei[E + e];   // dst
        if (j >= (unsigned)n || i >= (unsigned)n) continue;
        const float4* pa = fa + i * 8;
        const float4* pb = fb + j * 8;
        float u[32];
#pragma unroll
        for (int q = 0; q < 8; q++) {
            float4 a = pa[q], b = pb[q];
            u[4 * q + 0] = fmaxf(a.x + b.x, 0.f);
            u[4 * q + 1] = fmaxf(a.y + b.y, 0.f);
            u[4 * q + 2] = fmaxf(a.z + b.z, 0.f);
            u[4 * q + 3] = fmaxf(a.w + b.w, 0.f);
        }
        float p0 = 0.f, p1 = 0.f, p2 = 0.f, p3 = 0.f;
#pragma unroll
        for (int k0 = 0; k0 < 32; k0 += 8) {
            float v[8];
#pragma unroll
            for (int kk = 0; kk < 8; kk++) v[kk] = sb2[k0 + kk];
#pragma unroll
            for (int q = 0; q < 8; q++) {
#pragma unroll
                for (int kk = 0; kk < 8; kk++) {
                    float4 w = sw2[(k0 + kk) * 8 + q];
                    v[kk] += w.x * u[4 * q + 0] + w.y * u[4 * q + 1]
                           + w.z * u[4 * q + 2] + w.w * u[4 * q + 3];
                }
            }
#pragma unroll
            for (int kk = 0; kk < 8; kk++) {
                float vr = fmaxf(v[kk], 0.f);
                float4 c = spt[k0 + kk];
                p0 += c.x * vr;
                p1 += c.y * vr;
                p2 += c.z * vr;
                p3 += c.w * vr;
            }
        }
        red_add_v4(acc + 4 * i, p0, p1, p2, p3);
    }
}

// ---------------- finalize encoder: mu/logvar, reparam z, decoder layer-1 precompute ----------------
__global__ void k_fin1(const float2* __restrict__ eps,
                       const float* __restrict__ mu_b, const float* __restrict__ var_b,
                       const float* __restrict__ dw1, const float* __restrict__ db1,
                       float* __restrict__ out, int n, int out_size) {
    __shared__ float sw[128];   // dec_w1 (32 x 4)
    __shared__ float sb[32];
    __shared__ float sc[4];
    int tid = threadIdx.x;
    if (tid < 128) sw[tid] = dw1[tid];
    if (tid < 32)  sb[tid] = db1[tid];
    if (tid < 2) { sc[tid] = mu_b[tid]; sc[2 + tid] = var_b[tid]; }
    __syncthreads();
    bool write_heads = (out_size >= 8 * n);
    float2* out_mu = (float2*)(out + 4 * n);
    float2* out_lv = (float2*)(out + 6 * n);
    int t = blockIdx.x * blockDim.x + tid;
    int stride = gridDim.x * blockDim.x;
    for (int i = t; i < n; i += stride) {
        float4 a = g_enc_acc[i];
        float inv = 1.0f / fmaxf(g_deg[i], 1.0f);
        float mu0 = a.x * inv + sc[0];
        float mu1 = a.y * inv + sc[1];
        float lv0 = a.z * inv + sc[2];
        float lv1 = a.w * inv + sc[3];
        float2 ep = eps[i];
        float z0 = mu0 + ep.x * expf(0.5f * lv0);
        float z1 = mu1 + ep.y * expf(0.5f * lv1);
        if (write_heads) {
            out_mu[i] = make_float2(mu0, mu1);
            out_lv[i] = make_float2(lv0, lv1);
        }
        float4 ra[8], rb[8];
        float* pa = (float*)ra;
        float* pb = (float*)rb;
#pragma unroll
        for (int k = 0; k < 32; k++) {
            const float* w = sw + k * 4;
            float b = w[2] * z0 + w[3] * z1;
            float aa = sb[k] + w[0] * z0 + w[1] * z1 - b;
            pa[k] = aa;
            pb[k] = b;
        }
#pragma unroll
        for (int q8 = 0; q8 < 8; q8++) {
            g_da[i * 8 + q8] = ra[q8];
            g_db[i * 8 + q8] = rb[q8];
        }
    }
}

// ---------------- finalize decoder output ----------------
__global__ void k_fin2(const float* __restrict__ b3, float4* __restrict__ out, int n) {
    int t = blockIdx.x * blockDim.x + threadIdx.x;
    int stride = gridDim.x * blockDim.x;
    float c0 = b3[0], c1 = b3[1], c2 = b3[2], c3 = b3[3];
    for (int i = t; i < n; i += stride) {
        float4 a = g_dec_acc[i];
        float d = g_deg[i];
        float4 o;
        if (d > 0.5f) {
            float inv = 1.0f / d;
            o = make_float4(a.x * inv + c0, a.y * inv + c1, a.z * inv + c2, a.w * inv + c3);
        } else {
            o = make_float4(0.f, 0.f, 0.f, 0.f);
        }
        out[i] = o;
    }
}

// ---------------- launch ----------------
extern "C" void kernel_launch(void* const* d_in, const int* in_sizes, int n_in,
                              void* d_out, int out_size) {
    const float* x     = (const float*)d_in[0];
    const float* eps   = (const float*)d_in[1];
    const float* gamma = (const float*)d_in[2];
    const float* beta  = (const float*)d_in[3];
    const float* ew1   = (const float*)d_in[4];
    const float* eb1   = (const float*)d_in[5];
    const float* ew2   = (const float*)d_in[6];
    const float* eb2   = (const float*)d_in[7];
    const float* muw   = (const float*)d_in[8];
    const float* mub   = (const float*)d_in[9];
    const float* vw    = (const float*)d_in[10];
    const float* vb    = (const float*)d_in[11];
    const float* dw1   = (const float*)d_in[12];
    const float* db1   = (const float*)d_in[13];
    const float* dw2   = (const float*)d_in[14];
    const float* db2   = (const float*)d_in[15];
    const float* dw3   = (const float*)d_in[16];
    const float* db3   = (const float*)d_in[17];
    const int*   ei    = (const int*)d_in[18];   // int32: JAX x64 disabled downcasts int64

    int n = in_sizes[0] / 4;
    int E = in_sizes[18] / 2;
    float* out = (float*)d_out;

    k_zero<<<256, 256>>>(n);
    k_bn_reduce<<<160, 256>>>((const float4*)x, n);
    k_deg<<<1024, 256>>>(ei + E, E, n);
    k_prep_enc<<<256, 256>>>((const float4*)x, ew1, eb1, gamma, beta, n);

    int eblocks = 2368;  // grid-stride over 3.2M edges
    k_edge<0><<<eblocks, 256>>>(ei, E, n, ew2, eb2, muw, vw);
    k_fin1<<<256, 256>>>((const float2*)eps, mub, vb, dw1, db1, out, n, out_size);
    k_edge<1><<<eblocks, 256>>>(ei, E, n, dw2, db2, dw3, dw3 + 64);
    k_fin2<<<128, 256>>>(db3, (float4*)out, n);
}

// round 3
// speedup vs baseline: 1.0567x; 1.0567x over previous
#include <cuda_runtime.h>

#define MAXN 100000
typedef unsigned long long ull;

// ---------------- device scratch (static: no allocations allowed) ----------------
__device__ float  g_bn[8];              // sum[4], sumsq[4]
__device__ float  g_deg[MAXN];
__device__ float4 g_enc_acc[MAXN];      // {mu0,mu1,lv0,lv1} sums
__device__ float4 g_dec_acc[MAXN];      // {o0..o3} sums
__device__ float4 g_ea[MAXN * 8];       // A@xn + b1  (N x 32)
__device__ float4 g_eb[MAXN * 8];       // B@xn       (N x 32)
__device__ float4 g_da[MAXN * 8];       // decoder A@z + b1
__device__ float4 g_db[MAXN * 8];       // decoder B@z

__device__ __forceinline__ void red_add_v4(float* p, float a, float b, float c, float d) {
    asm volatile("red.global.add.v4.f32 [%0], {%1,%2,%3,%4};"
                 :: "l"(p), "f"(a), "f"(b), "f"(c), "f"(d) : "memory");
}
__device__ __forceinline__ void red_add_f32(float* p, float a) {
    asm volatile("red.global.add.f32 [%0], %1;" :: "l"(p), "f"(a) : "memory");
}
__device__ __forceinline__ ull pack2(float lo, float hi) {
    ull d;
    asm("mov.b64 %0, {%1, %2};" : "=l"(d) : "f"(lo), "f"(hi));
    return d;
}
__device__ __forceinline__ ull packdup(float x) {
    ull d;
    asm("mov.b64 %0, {%1, %1};" : "=l"(d) : "f"(x));
    return d;
}
__device__ __forceinline__ void unpack2(ull v, float& lo, float& hi) {
    asm("mov.b64 {%0, %1}, %2;" : "=f"(lo), "=f"(hi) : "l"(v));
}
__device__ __forceinline__ ull fma2(ull a, ull b, ull c) {
    ull d;
    asm("fma.rn.f32x2 %0, %1, %2, %3;" : "=l"(d) : "l"(a), "l"(b), "l"(c));
    return d;
}

// ---------------- zero accumulators ----------------
__global__ void k_zero(int n) {
    int t = blockIdx.x * blockDim.x + threadIdx.x;
    int stride = gridDim.x * blockDim.x;
    float4 z = make_float4(0.f, 0.f, 0.f, 0.f);
    for (int i = t; i < n; i += stride) {
        g_enc_acc[i] = z;
        g_dec_acc[i] = z;
        g_deg[i] = 0.f;
    }
    if (t < 8) g_bn[t] = 0.f;
}

// ---------------- batchnorm statistics ----------------
__global__ void k_bn_reduce(const float4* __restrict__ x, int n) {
    int t = blockIdx.x * blockDim.x + threadIdx.x;
    int stride = gridDim.x * blockDim.x;
    float s[4] = {0.f, 0.f, 0.f, 0.f};
    float q[4] = {0.f, 0.f, 0.f, 0.f};
    for (int i = t; i < n; i += stride) {
        float4 v = x[i];
        s[0] += v.x; q[0] += v.x * v.x;
        s[1] += v.y; q[1] += v.y * v.y;
        s[2] += v.z; q[2] += v.z * v.z;
        s[3] += v.w; q[3] += v.w * v.w;
    }
#pragma unroll
    for (int o = 16; o > 0; o >>= 1) {
#pragma unroll
        for (int c = 0; c < 4; c++) {
            s[c] += __shfl_down_sync(0xffffffffu, s[c], o);
            q[c] += __shfl_down_sync(0xffffffffu, q[c], o);
        }
    }
    if ((threadIdx.x & 31) == 0) {
#pragma unroll
        for (int c = 0; c < 4; c++) {
            atomicAdd(&g_bn[c], s[c]);
            atomicAdd(&g_bn[4 + c], q[c]);
        }
    }
}

// ---------------- encoder node precompute: BN + linearized layer 1 ----------------
__global__ void k_prep_enc(const float4* __restrict__ x,
                           const float* __restrict__ w1, const float* __restrict__ b1,
                           const float* __restrict__ gamma, const float* __restrict__ beta,
                           int n) {
    __shared__ float sw[256];   // enc_w1 (32 x 8) row-major
    __shared__ float sb1[32];
    __shared__ float sm[4], ss[4], sbt[4];
    int tid = threadIdx.x;
    if (tid < 256) sw[tid] = w1[tid];
    if (tid < 32)  sb1[tid] = b1[tid];
    if (tid < 4) {
        float m = g_bn[tid] / (float)n;
        float var = g_bn[4 + tid] / (float)n - m * m;
        sm[tid]  = m;
        ss[tid]  = rsqrtf(var + 1e-5f) * gamma[tid];
        sbt[tid] = beta[tid];
    }
    __syncthreads();
    int t = blockIdx.x * blockDim.x + tid;
    int stride = gridDim.x * blockDim.x;
    for (int i = t; i < n; i += stride) {
        float4 xv = x[i];
        float x0 = (xv.x - sm[0]) * ss[0] + sbt[0];
        float x1 = (xv.y - sm[1]) * ss[1] + sbt[1];
        float x2 = (xv.z - sm[2]) * ss[2] + sbt[2];
        float x3 = (xv.w - sm[3]) * ss[3] + sbt[3];
        float4 ra[8], rb[8];
        float* pa = (float*)ra;
        float* pb = (float*)rb;
#pragma unroll
        for (int k = 0; k < 32; k++) {
            const float* w = sw + k * 8;
            float b = w[4] * x0 + w[5] * x1 + w[6] * x2 + w[7] * x3;
            float a = sb1[k] + w[0] * x0 + w[1] * x1 + w[2] * x2 + w[3] * x3 - b;
            pa[k] = a;
            pb[k] = b;
        }
#pragma unroll
        for (int q8 = 0; q8 < 8; q8++) {
            g_ea[i * 8 + q8] = ra[q8];
            g_eb[i * 8 + q8] = rb[q8];
        }
    }
}

// ---------------- unified per-edge kernel (PHASE 0 = encoder, 1 = decoder) ----------------
// u = relu(fa[dst] + fb[src]); v = relu(W2 @ u + b2); p = [pA; pB] @ v;  red.v4 -> acc[dst]
// Packed f32x2: W2 pre-interleaved in shared as output-pairs; 512 FMA2 per edge.
template <int PHASE>
__global__ void __launch_bounds__(256)
k_edge(const int* __restrict__ ei, int E, int n,
       const float* __restrict__ w2, const float* __restrict__ b2,
       const float* __restrict__ pA, const float* __restrict__ pB) {
    // swp2[j*8 + kpp]: .x = {w2[4kpp+0][j], w2[4kpp+1][j]}, .y = {w2[4kpp+2][j], w2[4kpp+3][j]}
    __shared__ longlong2 swp2[256];
    __shared__ ull sb2p[16];    // {b2[2kp], b2[2kp+1]}
    __shared__ ull spAp[32];    // {pA[k], pA[32+k]}  (mu rows / dec rows 0,1)
    __shared__ ull spBp[32];    // {pB[k], pB[32+k]}  (logvar rows / dec rows 2,3)
    int tid = threadIdx.x;
    {
        int j = tid >> 3, kpp = tid & 7;
        longlong2 w;
        w.x = (long long)pack2(w2[(4 * kpp + 0) * 32 + j], w2[(4 * kpp + 1) * 32 + j]);
        w.y = (long long)pack2(w2[(4 * kpp + 2) * 32 + j], w2[(4 * kpp + 3) * 32 + j]);
        swp2[tid] = w;
    }
    if (tid < 16) sb2p[tid] = pack2(b2[2 * tid], b2[2 * tid + 1]);
    if (tid < 32) {
        spAp[tid] = pack2(pA[tid], pA[32 + tid]);
        spBp[tid] = pack2(pB[tid], pB[32 + tid]);
    }
    __syncthreads();

    const float4* fa = (PHASE == 0) ? g_ea : g_da;
    const float4* fb = (PHASE == 0) ? g_eb : g_db;
    float* acc = (PHASE == 0) ? (float*)g_enc_acc : (float*)g_dec_acc;

    int t = blockIdx.x * blockDim.x + tid;
    int stride = gridDim.x * blockDim.x;
    for (int e = t; e < E; e += stride) {
        unsigned j = (unsigned)ei[e];       // src
        unsigned i = (unsigned)ei[E + e];   // dst
        if (j >= (unsigned)n || i >= (unsigned)n) continue;
        const float4* pa = fa + i * 8;
        const float4* pb = fb + j * 8;

        ull v2[16];
#pragma unroll
        for (int kp = 0; kp < 16; kp++) v2[kp] = sb2p[kp];

        float4 a0 = pa[0], b0 = pb[0];
#pragma unroll
        for (int q = 0; q < 8; q++) {
            float4 an, bn;
            if (q < 7) { an = pa[q + 1]; bn = pb[q + 1]; }
            float uq[4];
            uq[0] = fmaxf(a0.x + b0.x, 0.f);
            uq[1] = fmaxf(a0.y + b0.y, 0.f);
            uq[2] = fmaxf(a0.z + b0.z, 0.f);
            uq[3] = fmaxf(a0.w + b0.w, 0.f);
#pragma unroll
            for (int jj = 0; jj < 4; jj++) {
                ull u2 = packdup(uq[jj]);
                const longlong2* wrow = swp2 + (4 * q + jj) * 8;
#pragma unroll
                for (int kpp = 0; kpp < 8; kpp++) {
                    longlong2 w = wrow[kpp];
                    v2[2 * kpp + 0] = fma2((ull)w.x, u2, v2[2 * kpp + 0]);
                    v2[2 * kpp + 1] = fma2((ull)w.y, u2, v2[2 * kpp + 1]);
                }
            }
            a0 = an; b0 = bn;
        }

        ull p01 = 0, p23 = 0;   // bit pattern 0 == {0.f, 0.f}
#pragma unroll
        for (int kp = 0; kp < 16; kp++) {
            float f0, f1;
            unpack2(v2[kp], f0, f1);
            f0 = fmaxf(f0, 0.f);
            f1 = fmaxf(f1, 0.f);
            ull vr0 = packdup(f0), vr1 = packdup(f1);
            p01 = fma2(spAp[2 * kp + 0], vr0, p01);
            p23 = fma2(spBp[2 * kp + 0], vr0, p23);
            p01 = fma2(spAp[2 * kp + 1], vr1, p01);
            p23 = fma2(spBp[2 * kp + 1], vr1, p23);
        }
        float p0, p1, p2, p3;
        unpack2(p01, p0, p1);
        unpack2(p23, p2, p3);
        red_add_v4(acc + 4 * i, p0, p1, p2, p3);
        if (PHASE == 0) red_add_f32(&g_deg[i], 1.0f);
    }
}

// ---------------- finalize encoder: mu/logvar, reparam z, decoder layer-1 precompute ----------------
__global__ void k_fin1(const float2* __restrict__ eps,
                       const float* __restrict__ mu_b, const float* __restrict__ var_b,
                       const float* __restrict__ dw1, const float* __restrict__ db1,
                       float* __restrict__ out, int n, int out_size) {
    __shared__ float sw[128];   // dec_w1 (32 x 4)
    __shared__ float sb[32];
    __shared__ float sc[4];
    int tid = threadIdx.x;
    if (tid < 128) sw[tid] = dw1[tid];
    if (tid < 32)  sb[tid] = db1[tid];
    if (tid < 2) { sc[tid] = mu_b[tid]; sc[2 + tid] = var_b[tid]; }
    __syncthreads();
    bool write_heads = (out_size >= 8 * n);
    float2* out_mu = (float2*)(out + 4 * n);
    float2* out_lv = (float2*)(out + 6 * n);
    int t = blockIdx.x * blockDim.x + tid;
    int stride = gridDim.x * blockDim.x;
    for (int i = t; i < n; i += stride) {
        float4 a = g_enc_acc[i];
        float inv = 1.0f / fmaxf(g_deg[i], 1.0f);
        float mu0 = a.x * inv + sc[0];
        float mu1 = a.y * inv + sc[1];
        float lv0 = a.z * inv + sc[2];
        float lv1 = a.w * inv + sc[3];
        float2 ep = eps[i];
        float z0 = mu0 + ep.x * expf(0.5f * lv0);
        float z1 = mu1 + ep.y * expf(0.5f * lv1);
        if (write_heads) {
            out_mu[i] = make_float2(mu0, mu1);
            out_lv[i] = make_float2(lv0, lv1);
        }
        float4 ra[8], rb[8];
        float* pa = (float*)ra;
        float* pb = (float*)rb;
#pragma unroll
        for (int k = 0; k < 32; k++) {
            const float* w = sw + k * 4;
            float b = w[2] * z0 + w[3] * z1;
            float aa = sb[k] + w[0] * z0 + w[1] * z1 - b;
            pa[k] = aa;
            pb[k] = b;
        }
#pragma unroll
        for (int q8 = 0; q8 < 8; q8++) {
            g_da[i * 8 + q8] = ra[q8];
            g_db[i * 8 + q8] = rb[q8];
        }
    }
}

// ---------------- finalize decoder output ----------------
__global__ void k_fin2(const float* __restrict__ b3, float4* __restrict__ out, int n) {
    int t = blockIdx.x * blockDim.x + threadIdx.x;
    int stride = gridDim.x * blockDim.x;
    float c0 = b3[0], c1 = b3[1], c2 = b3[2], c3 = b3[3];
    for (int i = t; i < n; i += stride) {
        float4 a = g_dec_acc[i];
        float d = g_deg[i];
        float4 o;
        if (d > 0.5f) {
            float inv = 1.0f / d;
            o = make_float4(a.x * inv + c0, a.y * inv + c1, a.z * inv + c2, a.w * inv + c3);
        } else {
            o = make_float4(0.f, 0.f, 0.f, 0.f);
        }
        out[i] = o;
    }
}

// ---------------- launch ----------------
extern "C" void kernel_launch(void* const* d_in, const int* in_sizes, int n_in,
                              void* d_out, int out_size) {
    const float* x     = (const float*)d_in[0];
    const float* eps   = (const float*)d_in[1];
    const float* gamma = (const float*)d_in[2];
    const float* beta  = (const float*)d_in[3];
    const float* ew1   = (const float*)d_in[4];
    const float* eb1   = (const float*)d_in[5];
    const float* ew2   = (const float*)d_in[6];
    const float* eb2   = (const float*)d_in[7];
    const float* muw   = (const float*)d_in[8];
    const float* mub   = (const float*)d_in[9];
    const float* vw    = (const float*)d_in[10];
    const float* vb    = (const float*)d_in[11];
    const float* dw1   = (const float*)d_in[12];
    const float* db1   = (const float*)d_in[13];
    const float* dw2   = (const float*)d_in[14];
    const float* db2   = (const float*)d_in[15];
    const float* dw3   = (const float*)d_in[16];
    const float* db3   = (const float*)d_in[17];
    const int*   ei    = (const int*)d_in[18];   // int32

    int n = in_sizes[0] / 4;
    int E = in_sizes[18] / 2;
    float* out = (float*)d_out;

    k_zero<<<256, 256>>>(n);
    k_bn_reduce<<<160, 256>>>((const float4*)x, n);
    k_prep_enc<<<256, 256>>>((const float4*)x, ew1, eb1, gamma, beta, n);

    int eblocks = 2368;  // grid-stride over 3.2M edges
    k_edge<0><<<eblocks, 256>>>(ei, E, n, ew2, eb2, muw, vw);
    k_fin1<<<256, 256>>>((const float2*)eps, mub, vb, dw1, db1, out, n, out_size);
    k_edge<1><<<eblocks, 256>>>(ei, E, n, dw2, db2, dw3, dw3 + 64);
    k_fin2<<<128, 256>>>(db3, (float4*)out, n);
}

// round 4
// speedup vs baseline: 1.3443x; 1.2723x over previous
#include <cuda_runtime.h>

#define MAXN 100000
typedef unsigned long long ull;

// ---------------- device scratch (static: no allocations allowed) ----------------
__device__ float  g_bn[8];              // sum[4], sumsq[4]
__device__ float  g_deg[MAXN];
__device__ float4 g_enc_acc[MAXN];      // {mu0,mu1,lv0,lv1} sums
__device__ float4 g_dec_acc[MAXN];      // {o0..o3} sums
__device__ float4 g_ea[MAXN * 8];       // A@xn + b1  (N x 32)
__device__ float4 g_eb[MAXN * 8];       // B@xn       (N x 32)
__device__ float4 g_da[MAXN * 8];       // decoder A@z + b1
__device__ float4 g_db[MAXN * 8];       // decoder B@z

__device__ __forceinline__ void red_add_v4(float* p, float a, float b, float c, float d) {
    asm volatile("red.global.add.v4.f32 [%0], {%1,%2,%3,%4};"
                 :: "l"(p), "f"(a), "f"(b), "f"(c), "f"(d) : "memory");
}
__device__ __forceinline__ void red_add_f32(float* p, float a) {
    asm volatile("red.global.add.f32 [%0], %1;" :: "l"(p), "f"(a) : "memory");
}
__device__ __forceinline__ ull pack2(float lo, float hi) {
    ull d;
    asm("mov.b64 %0, {%1, %2};" : "=l"(d) : "f"(lo), "f"(hi));
    return d;
}
__device__ __forceinline__ ull packdup(float x) {
    ull d;
    asm("mov.b64 %0, {%1, %1};" : "=l"(d) : "f"(x));
    return d;
}
__device__ __forceinline__ void unpack2(ull v, float& lo, float& hi) {
    asm("mov.b64 {%0, %1}, %2;" : "=f"(lo), "=f"(hi) : "l"(v));
}
__device__ __forceinline__ ull fma2(ull a, ull b, ull c) {
    ull d;
    asm("fma.rn.f32x2 %0, %1, %2, %3;" : "=l"(d) : "l"(a), "l"(b), "l"(c));
    return d;
}

// ---------------- zero accumulators ----------------
__global__ void k_zero(int n) {
    int t = blockIdx.x * blockDim.x + threadIdx.x;
    int stride = gridDim.x * blockDim.x;
    float4 z = make_float4(0.f, 0.f, 0.f, 0.f);
    for (int i = t; i < n; i += stride) {
        g_enc_acc[i] = z;
        g_dec_acc[i] = z;
        g_deg[i] = 0.f;
    }
    if (t < 8) g_bn[t] = 0.f;
}

// ---------------- batchnorm statistics ----------------
__global__ void k_bn_reduce(const float4* __restrict__ x, int n) {
    int t = blockIdx.x * blockDim.x + threadIdx.x;
    int stride = gridDim.x * blockDim.x;
    float s[4] = {0.f, 0.f, 0.f, 0.f};
    float q[4] = {0.f, 0.f, 0.f, 0.f};
    for (int i = t; i < n; i += stride) {
        float4 v = x[i];
        s[0] += v.x; q[0] += v.x * v.x;
        s[1] += v.y; q[1] += v.y * v.y;
        s[2] += v.z; q[2] += v.z * v.z;
        s[3] += v.w; q[3] += v.w * v.w;
    }
#pragma unroll
    for (int o = 16; o > 0; o >>= 1) {
#pragma unroll
        for (int c = 0; c < 4; c++) {
            s[c] += __shfl_down_sync(0xffffffffu, s[c], o);
            q[c] += __shfl_down_sync(0xffffffffu, q[c], o);
        }
    }
    if ((threadIdx.x & 31) == 0) {
#pragma unroll
        for (int c = 0; c < 4; c++) {
            atomicAdd(&g_bn[c], s[c]);
            atomicAdd(&g_bn[4 + c], q[c]);
        }
    }
}

// ---------------- encoder node precompute: BN + linearized layer 1 ----------------
__global__ void k_prep_enc(const float4* __restrict__ x,
                           const float* __restrict__ w1, const float* __restrict__ b1,
                           const float* __restrict__ gamma, const float* __restrict__ beta,
                           int n) {
    __shared__ float sw[256];   // enc_w1 (32 x 8) row-major
    __shared__ float sb1[32];
    __shared__ float sm[4], ss[4], sbt[4];
    int tid = threadIdx.x;
    if (tid < 256) sw[tid] = w1[tid];
    if (tid < 32)  sb1[tid] = b1[tid];
    if (tid < 4) {
        float m = g_bn[tid] / (float)n;
        float var = g_bn[4 + tid] / (float)n - m * m;
        sm[tid]  = m;
        ss[tid]  = rsqrtf(var + 1e-5f) * gamma[tid];
        sbt[tid] = beta[tid];
    }
    __syncthreads();
    int t = blockIdx.x * blockDim.x + tid;
    int stride = gridDim.x * blockDim.x;
    for (int i = t; i < n; i += stride) {
        float4 xv = x[i];
        float x0 = (xv.x - sm[0]) * ss[0] + sbt[0];
        float x1 = (xv.y - sm[1]) * ss[1] + sbt[1];
        float x2 = (xv.z - sm[2]) * ss[2] + sbt[2];
        float x3 = (xv.w - sm[3]) * ss[3] + sbt[3];
        float4 ra[8], rb[8];
        float* pa = (float*)ra;
        float* pb = (float*)rb;
#pragma unroll
        for (int k = 0; k < 32; k++) {
            const float* w = sw + k * 8;
            float b = w[4] * x0 + w[5] * x1 + w[6] * x2 + w[7] * x3;
            float a = sb1[k] + w[0] * x0 + w[1] * x1 + w[2] * x2 + w[3] * x3 - b;
            pa[k] = a;
            pb[k] = b;
        }
#pragma unroll
        for (int q8 = 0; q8 < 8; q8++) {
            g_ea[i * 8 + q8] = ra[q8];
            g_eb[i * 8 + q8] = rb[q8];
        }
    }
}

// ---------------- unified per-edge kernel, 2 edges per thread ----------------
// Per edge: u = relu(fa[dst] + fb[src]); v = relu(W2@u + b2); p = [pA;pB]@v; red.v4 -> acc[dst]
// One pass over W2 in shared feeds BOTH edges' accumulators (halves LDS traffic/edge).
template <int PHASE>
__global__ void __launch_bounds__(256, 2)
k_edge(const int* __restrict__ ei, int E, int n,
       const float* __restrict__ w2, const float* __restrict__ b2,
       const float* __restrict__ pA, const float* __restrict__ pB) {
    // swp2[j*8 + kpp]: .x = {w2[4kpp+0][j], w2[4kpp+1][j]}, .y = {w2[4kpp+2][j], w2[4kpp+3][j]}
    __shared__ longlong2 swp2[256];
    __shared__ ull sb2p[16];        // {b2[2kp], b2[2kp+1]}
    __shared__ longlong2 sp2[32];   // sp2[k]: .x = {pA[k],pA[32+k]}, .y = {pB[k],pB[32+k]}
    int tid = threadIdx.x;
    {
        int j = tid >> 3, kpp = tid & 7;
        longlong2 w;
        w.x = (long long)pack2(w2[(4 * kpp + 0) * 32 + j], w2[(4 * kpp + 1) * 32 + j]);
        w.y = (long long)pack2(w2[(4 * kpp + 2) * 32 + j], w2[(4 * kpp + 3) * 32 + j]);
        swp2[tid] = w;
    }
    if (tid < 16) sb2p[tid] = pack2(b2[2 * tid], b2[2 * tid + 1]);
    if (tid < 32) {
        longlong2 c;
        c.x = (long long)pack2(pA[tid], pA[32 + tid]);
        c.y = (long long)pack2(pB[tid], pB[32 + tid]);
        sp2[tid] = c;
    }
    __syncthreads();

    const float4* fa = (PHASE == 0) ? g_ea : g_da;
    const float4* fb = (PHASE == 0) ? g_eb : g_db;
    float* acc = (PHASE == 0) ? (float*)g_enc_acc : (float*)g_dec_acc;

    int t = blockIdx.x * blockDim.x + tid;
    int stride = gridDim.x * blockDim.x;
    int P = (E + 1) >> 1;   // pairs (last may be degenerate)

    for (int p = t; p < P; p += stride) {
        int e0 = 2 * p;
        int e1 = e0 + 1;
        bool ok1 = (e1 < E);
        unsigned jA = (unsigned)ei[e0];
        unsigned iA = (unsigned)ei[E + e0];
        unsigned jB = ok1 ? (unsigned)ei[e1] : jA;
        unsigned iB = ok1 ? (unsigned)ei[E + e1] : iA;
        bool okA = (jA < (unsigned)n) && (iA < (unsigned)n);
        bool okB = ok1 && (jB < (unsigned)n) && (iB < (unsigned)n);
        if (!okA && !okB) continue;
        if (!okA) { jA = jB; iA = iB; }      // okB true here
        if (!okB) { jB = jA; iB = iA; }      // duplicate A, suppress B's write

        const float4* paA = fa + iA * 8;
        const float4* pbA = fb + jA * 8;
        const float4* paB = fa + iB * 8;
        const float4* pbB = fb + jB * 8;

        ull vA[16], vB[16];
#pragma unroll
        for (int kp = 0; kp < 16; kp++) { vA[kp] = sb2p[kp]; vB[kp] = vA[kp]; }

#pragma unroll
        for (int q = 0; q < 8; q++) {
            float4 a0 = paA[q], b0 = pbA[q];
            float4 a1 = paB[q], b1 = pbB[q];
            float uA[4], uB[4];
            uA[0] = fmaxf(a0.x + b0.x, 0.f);
            uA[1] = fmaxf(a0.y + b0.y, 0.f);
            uA[2] = fmaxf(a0.z + b0.z, 0.f);
            uA[3] = fmaxf(a0.w + b0.w, 0.f);
            uB[0] = fmaxf(a1.x + b1.x, 0.f);
            uB[1] = fmaxf(a1.y + b1.y, 0.f);
            uB[2] = fmaxf(a1.z + b1.z, 0.f);
            uB[3] = fmaxf(a1.w + b1.w, 0.f);
#pragma unroll
            for (int jj = 0; jj < 4; jj++) {
                ull uA2 = packdup(uA[jj]);
                ull uB2 = packdup(uB[jj]);
                const longlong2* wrow = swp2 + (4 * q + jj) * 8;
#pragma unroll
                for (int kpp = 0; kpp < 8; kpp++) {
                    longlong2 w = wrow[kpp];
                    vA[2 * kpp + 0] = fma2((ull)w.x, uA2, vA[2 * kpp + 0]);
                    vA[2 * kpp + 1] = fma2((ull)w.y, uA2, vA[2 * kpp + 1]);
                    vB[2 * kpp + 0] = fma2((ull)w.x, uB2, vB[2 * kpp + 0]);
                    vB[2 * kpp + 1] = fma2((ull)w.y, uB2, vB[2 * kpp + 1]);
                }
            }
        }

        ull pA01 = 0, pA23 = 0, pB01 = 0, pB23 = 0;
#pragma unroll
        for (int kp = 0; kp < 16; kp++) {
            longlong2 c0 = sp2[2 * kp + 0];
            longlong2 c1 = sp2[2 * kp + 1];
            float fA0, fA1, fB0, fB1;
            unpack2(vA[kp], fA0, fA1);
            unpack2(vB[kp], fB0, fB1);
            ull rA0 = packdup(fmaxf(fA0, 0.f));
            ull rA1 = packdup(fmaxf(fA1, 0.f));
            ull rB0 = packdup(fmaxf(fB0, 0.f));
            ull rB1 = packdup(fmaxf(fB1, 0.f));
            pA01 = fma2((ull)c0.x, rA0, pA01);
            pA23 = fma2((ull)c0.y, rA0, pA23);
            pA01 = fma2((ull)c1.x, rA1, pA01);
            pA23 = fma2((ull)c1.y, rA1, pA23);
            pB01 = fma2((ull)c0.x, rB0, pB01);
            pB23 = fma2((ull)c0.y, rB0, pB23);
            pB01 = fma2((ull)c1.x, rB1, pB01);
            pB23 = fma2((ull)c1.y, rB1, pB23);
        }

        float r0, r1, r2, r3;
        if (okA) {
            unpack2(pA01, r0, r1);
            unpack2(pA23, r2, r3);
            red_add_v4(acc + 4 * iA, r0, r1, r2, r3);
            if (PHASE == 0) red_add_f32(&g_deg[iA], 1.0f);
        }
        if (okB) {
            unpack2(pB01, r0, r1);
            unpack2(pB23, r2, r3);
            red_add_v4(acc + 4 * iB, r0, r1, r2, r3);
            if (PHASE == 0) red_add_f32(&g_deg[iB], 1.0f);
        }
    }
}

// ---------------- finalize encoder: mu/logvar, reparam z, decoder layer-1 precompute ----------------
__global__ void k_fin1(const float2* __restrict__ eps,
                       const float* __restrict__ mu_b, const float* __restrict__ var_b,
                       const float* __restrict__ dw1, const float* __restrict__ db1,
                       float* __restrict__ out, int n, int out_size) {
    __shared__ float sw[128];   // dec_w1 (32 x 4)
    __shared__ float sb[32];
    __shared__ float sc[4];
    int tid = threadIdx.x;
    if (tid < 128) sw[tid] = dw1[tid];
    if (tid < 32)  sb[tid] = db1[tid];
    if (tid < 2) { sc[tid] = mu_b[tid]; sc[2 + tid] = var_b[tid]; }
    __syncthreads();
    bool write_heads = (out_size >= 8 * n);
    float2* out_mu = (float2*)(out + 4 * n);
    float2* out_lv = (float2*)(out + 6 * n);
    int t = blockIdx.x * blockDim.x + tid;
    int stride = gridDim.x * blockDim.x;
    for (int i = t; i < n; i += stride) {
        float4 a = g_enc_acc[i];
        float inv = 1.0f / fmaxf(g_deg[i], 1.0f);
        float mu0 = a.x * inv + sc[0];
        float mu1 = a.y * inv + sc[1];
        float lv0 = a.z * inv + sc[2];
        float lv1 = a.w * inv + sc[3];
        float2 ep = eps[i];
        float z0 = mu0 + ep.x * expf(0.5f * lv0);
        float z1 = mu1 + ep.y * expf(0.5f * lv1);
        if (write_heads) {
            out_mu[i] = make_float2(mu0, mu1);
            out_lv[i] = make_float2(lv0, lv1);
        }
        float4 ra[8], rb[8];
        float* pa = (float*)ra;
        float* pb = (float*)rb;
#pragma unroll
        for (int k = 0; k < 32; k++) {
            const float* w = sw + k * 4;
            float b = w[2] * z0 + w[3] * z1;
            float aa = sb[k] + w[0] * z0 + w[1] * z1 - b;
            pa[k] = aa;
            pb[k] = b;
        }
#pragma unroll
        for (int q8 = 0; q8 < 8; q8++) {
            g_da[i * 8 + q8] = ra[q8];
            g_db[i * 8 + q8] = rb[q8];
        }
    }
}

// ---------------- finalize decoder output ----------------
__global__ void k_fin2(const float* __restrict__ b3, float4* __restrict__ out, int n) {
    int t = blockIdx.x * blockDim.x + threadIdx.x;
    int stride = gridDim.x * blockDim.x;
    float c0 = b3[0], c1 = b3[1], c2 = b3[2], c3 = b3[3];
    for (int i = t; i < n; i += stride) {
        float4 a = g_dec_acc[i];
        float d = g_deg[i];
        float4 o;
        if (d > 0.5f) {
            float inv = 1.0f / d;
            o = make_float4(a.x * inv + c0, a.y * inv + c1, a.z * inv + c2, a.w * inv + c3);
        } else {
            o = make_float4(0.f, 0.f, 0.f, 0.f);
        }
        out[i] = o;
    }
}

// ---------------- launch ----------------
extern "C" void kernel_launch(void* const* d_in, const int* in_sizes, int n_in,
                              void* d_out, int out_size) {
    const float* x     = (const float*)d_in[0];
    const float* eps   = (const float*)d_in[1];
    const float* gamma = (const float*)d_in[2];
    const float* beta  = (const float*)d_in[3];
    const float* ew1   = (const float*)d_in[4];
    const float* eb1   = (const float*)d_in[5];
    const float* ew2   = (const float*)d_in[6];
    const float* eb2   = (const float*)d_in[7];
    const float* muw   = (const float*)d_in[8];
    const float* mub   = (const float*)d_in[9];
    const float* vw    = (const float*)d_in[10];
    const float* vb    = (const float*)d_in[11];
    const float* dw1   = (const float*)d_in[12];
    const float* db1   = (const float*)d_in[13];
    const float* dw2   = (const float*)d_in[14];
    const float* db2   = (const float*)d_in[15];
    const float* dw3   = (const float*)d_in[16];
    const float* db3   = (const float*)d_in[17];
    const int*   ei    = (const int*)d_in[18];   // int32

    int n = in_sizes[0] / 4;
    int E = in_sizes[18] / 2;
    float* out = (float*)d_out;

    k_zero<<<256, 256>>>(n);
    k_bn_reduce<<<160, 256>>>((const float4*)x, n);
    k_prep_enc<<<256, 256>>>((const float4*)x, ew1, eb1, gamma, beta, n);

    int eblocks = 2368;  // grid-stride over 1.6M edge-pairs
    k_edge<0><<<eblocks, 256>>>(ei, E, n, ew2, eb2, muw, vw);
    k_fin1<<<256, 256>>>((const float2*)eps, mub, vb, dw1, db1, out, n, out_size);
    k_edge<1><<<eblocks, 256>>>(ei, E, n, dw2, db2, dw3, dw3 + 64);
    k_fin2<<<128, 256>>>(db3, (float4*)out, n);
}

// round 5
// speedup vs baseline: 2.1292x; 1.5838x over previous
#include <cuda_runtime.h>

#define MAXN 100000
typedef unsigned long long ull;

// ---------------- device scratch (static: no allocations allowed) ----------------
__device__ float  g_bn[8];              // sum[4], sumsq[4]
__device__ float  g_deg[MAXN];
__device__ float4 g_enc_acc[MAXN];      // {mu0,mu1,lv0,lv1} sums
__device__ float4 g_dec_acc[MAXN];      // {o0..o3} sums
__device__ float4 g_ea[MAXN * 8];       // A@xn + b1  (N x 32)
__device__ float4 g_eb[MAXN * 8];       // B@xn       (N x 32)
__device__ float4 g_da[MAXN * 8];       // decoder A@z + b1
__device__ float4 g_db[MAXN * 8];       // decoder B@z

__device__ __forceinline__ void red_add_v4(float* p, float a, float b, float c, float d) {
    asm volatile("red.global.add.v4.f32 [%0], {%1,%2,%3,%4};"
                 :: "l"(p), "f"(a), "f"(b), "f"(c), "f"(d) : "memory");
}
__device__ __forceinline__ void red_add_f32(float* p, float a) {
    asm volatile("red.global.add.f32 [%0], %1;" :: "l"(p), "f"(a) : "memory");
}
__device__ __forceinline__ ull pack2(float lo, float hi) {
    ull d;
    asm("mov.b64 %0, {%1, %2};" : "=l"(d) : "f"(lo), "f"(hi));
    return d;
}
__device__ __forceinline__ ull packdup(float x) {
    ull d;
    asm("mov.b64 %0, {%1, %1};" : "=l"(d) : "f"(x));
    return d;
}
__device__ __forceinline__ void unpack2(ull v, float& lo, float& hi) {
    asm("mov.b64 {%0, %1}, %2;" : "=f"(lo), "=f"(hi) : "l"(v));
}
__device__ __forceinline__ ull fma2(ull a, ull b, ull c) {
    ull d;
    asm("fma.rn.f32x2 %0, %1, %2, %3;" : "=l"(d) : "l"(a), "l"(b), "l"(c));
    return d;
}

// ---------------- zero accumulators ----------------
__global__ void k_zero(int n) {
    int t = blockIdx.x * blockDim.x + threadIdx.x;
    int stride = gridDim.x * blockDim.x;
    float4 z = make_float4(0.f, 0.f, 0.f, 0.f);
    for (int i = t; i < n; i += stride) {
        g_enc_acc[i] = z;
        g_dec_acc[i] = z;
        g_deg[i] = 0.f;
    }
    if (t < 8) g_bn[t] = 0.f;
}

// ---------------- batchnorm statistics ----------------
__global__ void k_bn_reduce(const float4* __restrict__ x, int n) {
    int t = blockIdx.x * blockDim.x + threadIdx.x;
    int stride = gridDim.x * blockDim.x;
    float s[4] = {0.f, 0.f, 0.f, 0.f};
    float q[4] = {0.f, 0.f, 0.f, 0.f};
    for (int i = t; i < n; i += stride) {
        float4 v = x[i];
        s[0] += v.x; q[0] += v.x * v.x;
        s[1] += v.y; q[1] += v.y * v.y;
        s[2] += v.z; q[2] += v.z * v.z;
        s[3] += v.w; q[3] += v.w * v.w;
    }
#pragma unroll
    for (int o = 16; o > 0; o >>= 1) {
#pragma unroll
        for (int c = 0; c < 4; c++) {
            s[c] += __shfl_down_sync(0xffffffffu, s[c], o);
            q[c] += __shfl_down_sync(0xffffffffu, q[c], o);
        }
    }
    if ((threadIdx.x & 31) == 0) {
#pragma unroll
        for (int c = 0; c < 4; c++) {
            atomicAdd(&g_bn[c], s[c]);
            atomicAdd(&g_bn[4 + c], q[c]);
        }
    }
}

// ---------------- encoder node precompute: BN + linearized layer 1 ----------------
__global__ void k_prep_enc(const float4* __restrict__ x,
                           const float* __restrict__ w1, const float* __restrict__ b1,
                           const float* __restrict__ gamma, const float* __restrict__ beta,
                           int n) {
    __shared__ float sw[256];   // enc_w1 (32 x 8) row-major
    __shared__ float sb1[32];
    __shared__ float sm[4], ss[4], sbt[4];
    int tid = threadIdx.x;
    if (tid < 256) sw[tid] = w1[tid];
    if (tid < 32)  sb1[tid] = b1[tid];
    if (tid < 4) {
        float m = g_bn[tid] / (float)n;
        float var = g_bn[4 + tid] / (float)n - m * m;
        sm[tid]  = m;
        ss[tid]  = rsqrtf(var + 1e-5f) * gamma[tid];
        sbt[tid] = beta[tid];
    }
    __syncthreads();
    int t = blockIdx.x * blockDim.x + tid;
    int stride = gridDim.x * blockDim.x;
    for (int i = t; i < n; i += stride) {
        float4 xv = x[i];
        float x0 = (xv.x - sm[0]) * ss[0] + sbt[0];
        float x1 = (xv.y - sm[1]) * ss[1] + sbt[1];
        float x2 = (xv.z - sm[2]) * ss[2] + sbt[2];
        float x3 = (xv.w - sm[3]) * ss[3] + sbt[3];
        float4 ra[8], rb[8];
        float* pa = (float*)ra;
        float* pb = (float*)rb;
#pragma unroll
        for (int k = 0; k < 32; k++) {
            const float* w = sw + k * 8;
            float b = w[4] * x0 + w[5] * x1 + w[6] * x2 + w[7] * x3;
            float a = sb1[k] + w[0] * x0 + w[1] * x1 + w[2] * x2 + w[3] * x3 - b;
            pa[k] = a;
            pb[k] = b;
        }
#pragma unroll
        for (int q8 = 0; q8 < 8; q8++) {
            g_ea[i * 8 + q8] = ra[q8];
            g_eb[i * 8 + q8] = rb[q8];
        }
    }
}

// ---------------- per-edge kernel: coalesced staged gather + pair FMA2 compute ----------------
// Warp handles 64 edges/iter. Gather: 8 lanes per node row -> full-line LDG, fuse
// u = relu(fa[dst]+fb[src]) in regs, stage to smem (row stride 36 floats, conflict-free).
// Compute: thread-pair FMA2 MLP over W2 in shared (one W2 stream feeds 2 edges).
#define ROWSTRIDE 36
template <int PHASE>
__global__ void __launch_bounds__(128, 4)
k_edge(const int* __restrict__ ei, int E, int n,
       const float* __restrict__ w2, const float* __restrict__ b2,
       const float* __restrict__ pA, const float* __restrict__ pB) {
    // swp2[j*8 + kpp]: .x = {w2[4kpp+0][j], w2[4kpp+1][j]}, .y = {w2[4kpp+2][j], w2[4kpp+3][j]}
    __shared__ longlong2 swp2[256];
    __shared__ ull sb2p[16];        // {b2[2kp], b2[2kp+1]}
    __shared__ longlong2 sp2[32];   // sp2[k]: .x = {pA[k],pA[32+k]}, .y = {pB[k],pB[32+k]}
    __shared__ __align__(16) float su[4 * 64 * ROWSTRIDE];   // 4 warps x 64 rows x 144B
    int tid = threadIdx.x;
#pragma unroll
    for (int b = 0; b < 2; b++) {
        int idx = tid + b * 128;
        int j = idx >> 3, kpp = idx & 7;
        longlong2 w;
        w.x = (long long)pack2(w2[(4 * kpp + 0) * 32 + j], w2[(4 * kpp + 1) * 32 + j]);
        w.y = (long long)pack2(w2[(4 * kpp + 2) * 32 + j], w2[(4 * kpp + 3) * 32 + j]);
        swp2[idx] = w;
    }
    if (tid < 16) sb2p[tid] = pack2(b2[2 * tid], b2[2 * tid + 1]);
    if (tid < 32) {
        longlong2 c;
        c.x = (long long)pack2(pA[tid], pA[32 + tid]);
        c.y = (long long)pack2(pB[tid], pB[32 + tid]);
        sp2[tid] = c;
    }
    __syncthreads();

    const float4* fa = (PHASE == 0) ? g_ea : g_da;
    const float4* fb = (PHASE == 0) ? g_eb : g_db;
    float* acc = (PHASE == 0) ? (float*)g_enc_acc : (float*)g_dec_acc;

    int warp = tid >> 5, lane = tid & 31;
    float* stage = su + warp * 64 * ROWSTRIDE;
    int c8 = lane & 7;          // chunk id for gather
    int rsub = lane >> 3;       // row-within-group for gather

    int iters = (E + 63) >> 6;
    for (int it = blockIdx.x * 4 + warp; it < iters; it += gridDim.x * 4) {
        int e0 = it << 6;
        int eA = e0 + lane;
        int eB = e0 + 32 + lane;
        bool okA = (eA < E);
        bool okB = (eB < E);
        int eAc = okA ? eA : (E - 1);
        int eBc = okB ? eB : (E - 1);
        unsigned jA = (unsigned)ei[eAc];
        unsigned iA = (unsigned)ei[E + eAc];
        unsigned jB = (unsigned)ei[eBc];
        unsigned iB = (unsigned)ei[E + eBc];
        okA = okA && (jA < (unsigned)n) && (iA < (unsigned)n);
        okB = okB && (jB < (unsigned)n) && (iB < (unsigned)n);
        unsigned jAs = okA ? jA : 0u, iAs = okA ? iA : 0u;
        unsigned jBs = okB ? jB : 0u, iBs = okB ? iB : 0u;

        __syncwarp();   // WAR: prior iteration's compute reads of stage done

        // ---- staged gather: 2 halves x 8 groups; 8 lanes cooperate per row ----
#pragma unroll
        for (int h = 0; h < 2; h++) {
#pragma unroll
            for (int g = 0; g < 8; g++) {
                int er = 4 * g + rsub;   // edge-in-half 0..31
                unsigned nd = __shfl_sync(0xffffffffu, h ? iBs : iAs, er);
                unsigned ns = __shfl_sync(0xffffffffu, h ? jBs : jAs, er);
                float4 a = fa[nd * 8 + c8];
                float4 b = fb[ns * 8 + c8];
                float4 u;
                u.x = fmaxf(a.x + b.x, 0.f);
                u.y = fmaxf(a.y + b.y, 0.f);
                u.z = fmaxf(a.z + b.z, 0.f);
                u.w = fmaxf(a.w + b.w, 0.f);
                *(float4*)(stage + (h * 32 + er) * ROWSTRIDE + c8 * 4) = u;
            }
        }
        __syncwarp();

        // ---- pair compute: thread handles edges (e0+lane, e0+32+lane) ----
        const float* uArow = stage + lane * ROWSTRIDE;
        const float* uBrow = stage + (32 + lane) * ROWSTRIDE;

        ull vA[16], vB[16];
#pragma unroll
        for (int kp = 0; kp < 16; kp++) { vA[kp] = sb2p[kp]; vB[kp] = vA[kp]; }

#pragma unroll
        for (int q = 0; q < 8; q++) {
            float4 ua = *(const float4*)(uArow + q * 4);
            float4 ub = *(const float4*)(uBrow + q * 4);
            float uAq[4] = {ua.x, ua.y, ua.z, ua.w};
            float uBq[4] = {ub.x, ub.y, ub.z, ub.w};
#pragma unroll
            for (int jj = 0; jj < 4; jj++) {
                ull uA2 = packdup(uAq[jj]);
                ull uB2 = packdup(uBq[jj]);
                const longlong2* wrow = swp2 + (4 * q + jj) * 8;
#pragma unroll
                for (int kpp = 0; kpp < 8; kpp++) {
                    longlong2 w = wrow[kpp];
                    vA[2 * kpp + 0] = fma2((ull)w.x, uA2, vA[2 * kpp + 0]);
                    vA[2 * kpp + 1] = fma2((ull)w.y, uA2, vA[2 * kpp + 1]);
                    vB[2 * kpp + 0] = fma2((ull)w.x, uB2, vB[2 * kpp + 0]);
                    vB[2 * kpp + 1] = fma2((ull)w.y, uB2, vB[2 * kpp + 1]);
                }
            }
        }

        ull pA01 = 0, pA23 = 0, pB01 = 0, pB23 = 0;
#pragma unroll
        for (int kp = 0; kp < 16; kp++) {
            longlong2 c0 = sp2[2 * kp + 0];
            longlong2 c1 = sp2[2 * kp + 1];
            float fA0, fA1, fB0, fB1;
            unpack2(vA[kp], fA0, fA1);
            unpack2(vB[kp], fB0, fB1);
            ull rA0 = packdup(fmaxf(fA0, 0.f));
            ull rA1 = packdup(fmaxf(fA1, 0.f));
            ull rB0 = packdup(fmaxf(fB0, 0.f));
            ull rB1 = packdup(fmaxf(fB1, 0.f));
            pA01 = fma2((ull)c0.x, rA0, pA01);
            pA23 = fma2((ull)c0.y, rA0, pA23);
            pA01 = fma2((ull)c1.x, rA1, pA01);
            pA23 = fma2((ull)c1.y, rA1, pA23);
            pB01 = fma2((ull)c0.x, rB0, pB01);
            pB23 = fma2((ull)c0.y, rB0, pB23);
            pB01 = fma2((ull)c1.x, rB1, pB01);
            pB23 = fma2((ull)c1.y, rB1, pB23);
        }

        float r0, r1, r2, r3;
        if (okA) {
            unpack2(pA01, r0, r1);
            unpack2(pA23, r2, r3);
            red_add_v4(acc + 4 * iA, r0, r1, r2, r3);
            if (PHASE == 0) red_add_f32(&g_deg[iA], 1.0f);
        }
        if (okB) {
            unpack2(pB01, r0, r1);
            unpack2(pB23, r2, r3);
            red_add_v4(acc + 4 * iB, r0, r1, r2, r3);
            if (PHASE == 0) red_add_f32(&g_deg[iB], 1.0f);
        }
    }
}

// ---------------- finalize encoder: mu/logvar, reparam z, decoder layer-1 precompute ----------------
__global__ void k_fin1(const float2* __restrict__ eps,
                       const float* __restrict__ mu_b, const float* __restrict__ var_b,
                       const float* __restrict__ dw1, const float* __restrict__ db1,
                       float* __restrict__ out, int n, int out_size) {
    __shared__ float sw[128];   // dec_w1 (32 x 4)
    __shared__ float sb[32];
    __shared__ float sc[4];
    int tid = threadIdx.x;
    if (tid < 128) sw[tid] = dw1[tid];
    if (tid < 32)  sb[tid] = db1[tid];
    if (tid < 2) { sc[tid] = mu_b[tid]; sc[2 + tid] = var_b[tid]; }
    __syncthreads();
    bool write_heads = (out_size >= 8 * n);
    float2* out_mu = (float2*)(out + 4 * n);
    float2* out_lv = (float2*)(out + 6 * n);
    int t = blockIdx.x * blockDim.x + tid;
    int stride = gridDim.x * blockDim.x;
    for (int i = t; i < n; i += stride) {
        float4 a = g_enc_acc[i];
        float inv = 1.0f / fmaxf(g_deg[i], 1.0f);
        float mu0 = a.x * inv + sc[0];
        float mu1 = a.y * inv + sc[1];
        float lv0 = a.z * inv + sc[2];
        float lv1 = a.w * inv + sc[3];
        float2 ep = eps[i];
        float z0 = mu0 + ep.x * expf(0.5f * lv0);
        float z1 = mu1 + ep.y * expf(0.5f * lv1);
        if (write_heads) {
            out_mu[i] = make_float2(mu0, mu1);
            out_lv[i] = make_float2(lv0, lv1);
        }
        float4 ra[8], rb[8];
        float* pa = (float*)ra;
        float* pb = (float*)rb;
#pragma unroll
        for (int k = 0; k < 32; k++) {
            const float* w = sw + k * 4;
            float b = w[2] * z0 + w[3] * z1;
            float aa = sb[k] + w[0] * z0 + w[1] * z1 - b;
            pa[k] = aa;
            pb[k] = b;
        }
#pragma unroll
        for (int q8 = 0; q8 < 8; q8++) {
            g_da[i * 8 + q8] = ra[q8];
            g_db[i * 8 + q8] = rb[q8];
        }
    }
}

// ---------------- finalize decoder output ----------------
__global__ void k_fin2(const float* __restrict__ b3, float4* __restrict__ out, int n) {
    int t = blockIdx.x * blockDim.x + threadIdx.x;
    int stride = gridDim.x * blockDim.x;
    float c0 = b3[0], c1 = b3[1], c2 = b3[2], c3 = b3[3];
    for (int i = t; i < n; i += stride) {
        float4 a = g_dec_acc[i];
        float d = g_deg[i];
        float4 o;
        if (d > 0.5f) {
            float inv = 1.0f / d;
            o = make_float4(a.x * inv + c0, a.y * inv + c1, a.z * inv + c2, a.w * inv + c3);
        } else {
            o = make_float4(0.f, 0.f, 0.f, 0.f);
        }
        out[i] = o;
    }
}

// ---------------- launch ----------------
extern "C" void kernel_launch(void* const* d_in, const int* in_sizes, int n_in,
                              void* d_out, int out_size) {
    const float* x     = (const float*)d_in[0];
    const float* eps   = (const float*)d_in[1];
    const float* gamma = (const float*)d_in[2];
    const float* beta  = (const float*)d_in[3];
    const float* ew1   = (const float*)d_in[4];
    const float* eb1   = (const float*)d_in[5];
    const float* ew2   = (const float*)d_in[6];
    const float* eb2   = (const float*)d_in[7];
    const float* muw   = (const float*)d_in[8];
    const float* mub   = (const float*)d_in[9];
    const float* vw    = (const float*)d_in[10];
    const float* vb    = (const float*)d_in[11];
    const float* dw1   = (const float*)d_in[12];
    const float* db1   = (const float*)d_in[13];
    const float* dw2   = (const float*)d_in[14];
    const float* db2   = (const float*)d_in[15];
    const float* dw3   = (const float*)d_in[16];
    const float* db3   = (const float*)d_in[17];
    const int*   ei    = (const int*)d_in[18];   // int32

    int n = in_sizes[0] / 4;
    int E = in_sizes[18] / 2;
    float* out = (float*)d_out;

    k_zero<<<256, 256>>>(n);
    k_bn_reduce<<<160, 256>>>((const float4*)x, n);
    k_prep_enc<<<256, 256>>>((const float4*)x, ew1, eb1, gamma, beta, n);

    int eblocks = 1184;   // 4 warps/block, 64 edges per warp-iter
    k_edge<0><<<eblocks, 128>>>(ei, E, n, ew2, eb2, muw, vw);
    k_fin1<<<256, 256>>>((const float2*)eps, mub, vb, dw1, db1, out, n, out_size);
    k_edge<1><<<eblocks, 128>>>(ei, E, n, dw2, db2, dw3, dw3 + 64);
    k_fin2<<<128, 256>>>(db3, (float4*)out, n);
}

// round 7
// speedup vs baseline: 2.6488x; 1.2440x over previous
#include <cuda_runtime.h>
#include <cstdint>

#define MAXN 100000
typedef unsigned long long ull;

// ---------------- device scratch (static: no allocations allowed) ----------------
__device__ float  g_bn[8];              // sum[4], sumsq[4]
__device__ float  g_deg[MAXN];
__device__ float4 g_enc_acc[MAXN];      // {mu0,mu1,lv0,lv1} sums
__device__ float4 g_dec_acc[MAXN];      // {o0..o3} sums
__device__ float4 g_ea[MAXN * 8];       // A@xn + b1  (N x 32)
__device__ float4 g_eb[MAXN * 8];       // B@xn       (N x 32)
__device__ float4 g_da[MAXN * 8];       // decoder A@z + b1
__device__ float4 g_db[MAXN * 8];       // decoder B@z

__device__ __forceinline__ void red_add_v4(float* p, float a, float b, float c, float d) {
    asm volatile("red.global.add.v4.f32 [%0], {%1,%2,%3,%4};"
                 :: "l"(p), "f"(a), "f"(b), "f"(c), "f"(d) : "memory");
}
__device__ __forceinline__ void red_add_f32(float* p, float a) {
    asm volatile("red.global.add.f32 [%0], %1;" :: "l"(p), "f"(a) : "memory");
}
__device__ __forceinline__ ull pack2(float lo, float hi) {
    ull d;
    asm("mov.b64 %0, {%1, %2};" : "=l"(d) : "f"(lo), "f"(hi));
    return d;
}
__device__ __forceinline__ ull packdup(float x) {
    ull d;
    asm("mov.b64 %0, {%1, %1};" : "=l"(d) : "f"(x));
    return d;
}
__device__ __forceinline__ void unpack2(ull v, float& lo, float& hi) {
    asm("mov.b64 {%0, %1}, %2;" : "=f"(lo), "=f"(hi) : "l"(v));
}
__device__ __forceinline__ ull fma2(ull a, ull b, ull c) {
    ull d;
    asm("fma.rn.f32x2 %0, %1, %2, %3;" : "=l"(d) : "l"(a), "l"(b), "l"(c));
    return d;
}
__device__ __forceinline__ uint32_t f2tf32(float f) {
    uint32_t r;
    asm("cvt.rna.tf32.f32 %0, %1;" : "=r"(r) : "f"(f));
    return r;
}

// ---------------- zero accumulators ----------------
__global__ void k_zero(int n) {
    int t = blockIdx.x * blockDim.x + threadIdx.x;
    int stride = gridDim.x * blockDim.x;
    float4 z = make_float4(0.f, 0.f, 0.f, 0.f);
    for (int i = t; i < n; i += stride) {
        g_enc_acc[i] = z;
        g_dec_acc[i] = z;
        g_deg[i] = 0.f;
    }
    if (t < 8) g_bn[t] = 0.f;
}

// ---------------- batchnorm statistics ----------------
__global__ void k_bn_reduce(const float4* __restrict__ x, int n) {
    int t = blockIdx.x * blockDim.x + threadIdx.x;
    int stride = gridDim.x * blockDim.x;
    float s[4] = {0.f, 0.f, 0.f, 0.f};
    float q[4] = {0.f, 0.f, 0.f, 0.f};
    for (int i = t; i < n; i += stride) {
        float4 v = x[i];
        s[0] += v.x; q[0] += v.x * v.x;
        s[1] += v.y; q[1] += v.y * v.y;
        s[2] += v.z; q[2] += v.z * v.z;
        s[3] += v.w; q[3] += v.w * v.w;
    }
#pragma unroll
    for (int o = 16; o > 0; o >>= 1) {
#pragma unroll
        for (int c = 0; c < 4; c++) {
            s[c] += __shfl_down_sync(0xffffffffu, s[c], o);
            q[c] += __shfl_down_sync(0xffffffffu, q[c], o);
        }
    }
    if ((threadIdx.x & 31) == 0) {
#pragma unroll
        for (int c = 0; c < 4; c++) {
            atomicAdd(&g_bn[c], s[c]);
            atomicAdd(&g_bn[4 + c], q[c]);
        }
    }
}

// ---------------- encoder node precompute: BN + linearized layer 1 ----------------
__global__ void k_prep_enc(const float4* __restrict__ x,
                           const float* __restrict__ w1, const float* __restrict__ b1,
                           const float* __restrict__ gamma, const float* __restrict__ beta,
                           int n) {
    __shared__ float sw[256];   // enc_w1 (32 x 8) row-major
    __shared__ float sb1[32];
    __shared__ float sm[4], ss[4], sbt[4];
    int tid = threadIdx.x;
    if (tid < 256) sw[tid] = w1[tid];
    if (tid < 32)  sb1[tid] = b1[tid];
    if (tid < 4) {
        float m = g_bn[tid] / (float)n;
        float var = g_bn[4 + tid] / (float)n - m * m;
        sm[tid]  = m;
        ss[tid]  = rsqrtf(var + 1e-5f) * gamma[tid];
        sbt[tid] = beta[tid];
    }
    __syncthreads();
    int t = blockIdx.x * blockDim.x + tid;
    int stride = gridDim.x * blockDim.x;
    for (int i = t; i < n; i += stride) {
        float4 xv = x[i];
        float x0 = (xv.x - sm[0]) * ss[0] + sbt[0];
        float x1 = (xv.y - sm[1]) * ss[1] + sbt[1];
        float x2 = (xv.z - sm[2]) * ss[2] + sbt[2];
        float x3 = (xv.w - sm[3]) * ss[3] + sbt[3];
        float4 ra[8], rb[8];
        float* pa = (float*)ra;
        float* pb = (float*)rb;
#pragma unroll
        for (int k = 0; k < 32; k++) {
            const float* w = sw + k * 8;
            float b = w[4] * x0 + w[5] * x1 + w[6] * x2 + w[7] * x3;
            float a = sb1[k] + w[0] * x0 + w[1] * x1 + w[2] * x2 + w[3] * x3 - b;
            pa[k] = a;
            pb[k] = b;
        }
#pragma unroll
        for (int q8 = 0; q8 < 8; q8++) {
            g_ea[i * 8 + q8] = ra[q8];
            g_eb[i * 8 + q8] = rb[q8];
        }
    }
}

// ---------------- per-edge kernel: staged gather -> mma.sync tf32 -> project + RED ----
// Warp-tile = 32 edges (M=32). A = u rows [32x32] in warp-private smem stage;
// B = W2 [32x32] as persistent register fragments (4 N-tiles x 4 K-tiles).
// C layout (m16n8): lane g=l>>2, tg=l&3 holds rows {g, g+8} cols {2tg, 2tg+1} per N-tile.
// Epilogue: relu(v+b2), project to 4 outputs, shfl-reduce over tg, RED from tg==0.
#define RS 36
template <int PHASE>
__global__ void __launch_bounds__(128, 3)
k_edge(const int* __restrict__ ei, int E, int n,
       const float* __restrict__ w2, const float* __restrict__ b2,
       const float* __restrict__ pA, const float* __restrict__ pB) {
    __shared__ __align__(16) float su[4 * 32 * RS];
    int tid = threadIdx.x;
    int warp = tid >> 5, lane = tid & 31;
    int g = lane >> 2, tg = lane & 3;

    // Persistent B fragments: bf0/bf1[nt][kt] = w2[8nt+g][8kt+tg(+4)]
    uint32_t bf0[4][4], bf1[4][4];
#pragma unroll
    for (int nt = 0; nt < 4; nt++)
#pragma unroll
        for (int kt = 0; kt < 4; kt++) {
            bf0[nt][kt] = f2tf32(w2[(8 * nt + g) * 32 + 8 * kt + tg]);
            bf1[nt][kt] = f2tf32(w2[(8 * nt + g) * 32 + 8 * kt + tg + 4]);
        }
    // Projection coeffs + bias for this lane's 8 columns (idx: nt=idx>>1, col=8nt+2tg+(idx&1))
    ull pc01[8], pc23[8];
    float b2c[8];
#pragma unroll
    for (int idx = 0; idx < 8; idx++) {
        int c = (idx >> 1) * 8 + 2 * tg + (idx & 1);
        pc01[idx] = pack2(pA[c], pA[32 + c]);
        pc23[idx] = pack2(pB[c], pB[32 + c]);
        b2c[idx]  = b2[c];
    }

    const float4* fa = (PHASE == 0) ? g_ea : g_da;
    const float4* fb = (PHASE == 0) ? g_eb : g_db;
    float* acc = (PHASE == 0) ? (float*)g_enc_acc : (float*)g_dec_acc;

    float* stage = su + warp * 32 * RS;
    int c8 = lane & 7, rsub = lane >> 3;
    int ntiles = (E + 127) >> 7;
    const ull ONE = packdup(1.0f);

    for (int t = blockIdx.x; t < ntiles; t += gridDim.x) {
        int e = (t << 7) + (warp << 5) + lane;
        bool ok = (e < E);
        int ec = ok ? e : (E - 1);
        unsigned j = (unsigned)ei[ec];
        unsigned i = (unsigned)ei[E + ec];
        ok = ok && (j < (unsigned)n) && (i < (unsigned)n);
        unsigned js = ok ? j : 0u, is = ok ? i : 0u;
        unsigned oki = ok ? 1u : 0u;

        __syncwarp();   // stage is warp-private; prior iter reads done
#pragma unroll
        for (int gg = 0; gg < 8; gg++) {
            int er = 4 * gg + rsub;
            unsigned nd = __shfl_sync(0xffffffffu, is, er);
            unsigned ns = __shfl_sync(0xffffffffu, js, er);
            float4 a = fa[nd * 8 + c8];
            float4 b = fb[ns * 8 + c8];
            float4 u;
            u.x = fmaxf(a.x + b.x, 0.f);
            u.y = fmaxf(a.y + b.y, 0.f);
            u.z = fmaxf(a.z + b.z, 0.f);
            u.w = fmaxf(a.w + b.w, 0.f);
            *(float4*)(stage + er * RS + c8 * 4) = u;
        }
        __syncwarp();

#pragma unroll
        for (int mt = 0; mt < 2; mt++) {
            float c[4][4];
#pragma unroll
            for (int nt = 0; nt < 4; nt++)
#pragma unroll
                for (int q = 0; q < 4; q++) c[nt][q] = 0.f;

#pragma unroll
            for (int kt = 0; kt < 4; kt++) {
                const float* ab = stage + (mt * 16 + g) * RS + kt * 8 + tg;
                uint32_t a0 = f2tf32(ab[0]);
                uint32_t a1 = f2tf32(ab[8 * RS]);
                uint32_t a2 = f2tf32(ab[4]);
                uint32_t a3 = f2tf32(ab[8 * RS + 4]);
#pragma unroll
                for (int nt = 0; nt < 4; nt++) {
                    asm volatile(
                        "mma.sync.aligned.m16n8k8.row.col.f32.tf32.tf32.f32 "
                        "{%0,%1,%2,%3}, {%4,%5,%6,%7}, {%8,%9}, {%0,%1,%2,%3};"
                        : "+f"(c[nt][0]), "+f"(c[nt][1]), "+f"(c[nt][2]), "+f"(c[nt][3])
                        : "r"(a0), "r"(a1), "r"(a2), "r"(a3),
                          "r"(bf0[nt][kt]), "r"(bf1[nt][kt]));
                }
            }

            // epilogue: rows r0 = mt*16+g, r1 = mt*16+8+g
            ull p01a = 0, p23a = 0, p01b = 0, p23b = 0;
#pragma unroll
            for (int nt = 0; nt < 4; nt++) {
                float r0 = fmaxf(c[nt][0] + b2c[2 * nt], 0.f);
                float r1 = fmaxf(c[nt][1] + b2c[2 * nt + 1], 0.f);
                float r2 = fmaxf(c[nt][2] + b2c[2 * nt], 0.f);
                float r3 = fmaxf(c[nt][3] + b2c[2 * nt + 1], 0.f);
                p01a = fma2(pc01[2 * nt], packdup(r0), p01a);
                p23a = fma2(pc23[2 * nt], packdup(r0), p23a);
                p01a = fma2(pc01[2 * nt + 1], packdup(r1), p01a);
                p23a = fma2(pc23[2 * nt + 1], packdup(r1), p23a);
                p01b = fma2(pc01[2 * nt], packdup(r2), p01b);
                p23b = fma2(pc23[2 * nt], packdup(r2), p23b);
                p01b = fma2(pc01[2 * nt + 1], packdup(r3), p01b);
                p23b = fma2(pc23[2 * nt + 1], packdup(r3), p23b);
            }
            // reduce over tg (lanes xor 1, xor 2)
#pragma unroll
            for (int m = 1; m <= 2; m <<= 1) {
                p01a = fma2(ONE, __shfl_xor_sync(0xffffffffu, p01a, m), p01a);
                p23a = fma2(ONE, __shfl_xor_sync(0xffffffffu, p23a, m), p23a);
                p01b = fma2(ONE, __shfl_xor_sync(0xffffffffu, p01b, m), p01b);
                p23b = fma2(ONE, __shfl_xor_sync(0xffffffffu, p23b, m), p23b);
            }
            unsigned iR0  = __shfl_sync(0xffffffffu, is,  mt * 16 + g);
            unsigned okR0 = __shfl_sync(0xffffffffu, oki, mt * 16 + g);
            unsigned iR1  = __shfl_sync(0xffffffffu, is,  mt * 16 + 8 + g);
            unsigned okR1 = __shfl_sync(0xffffffffu, oki, mt * 16 + 8 + g);
            if (tg == 0) {
                float r0, r1, r2, r3;
                if (okR0) {
                    unpack2(p01a, r0, r1);
                    unpack2(p23a, r2, r3);
                    red_add_v4(acc + 4 * iR0, r0, r1, r2, r3);
                    if (PHASE == 0) red_add_f32(&g_deg[iR0], 1.0f);
                }
                if (okR1) {
                    unpack2(p01b, r0, r1);
                    unpack2(p23b, r2, r3);
                    red_add_v4(acc + 4 * iR1, r0, r1, r2, r3);
                    if (PHASE == 0) red_add_f32(&g_deg[iR1], 1.0f);
                }
            }
        }
    }
}

// ---------------- finalize encoder: mu/logvar, reparam z, decoder layer-1 precompute ----------------
__global__ void k_fin1(const float2* __restrict__ eps,
                       const float* __restrict__ mu_b, const float* __restrict__ var_b,
                       const float* __restrict__ dw1, const float* __restrict__ db1,
                       float* __restrict__ out, int n, int out_size) {
    __shared__ float sw[128];   // dec_w1 (32 x 4)
    __shared__ float sb[32];
    __shared__ float sc[4];
    int tid = threadIdx.x;
    if (tid < 128) sw[tid] = dw1[tid];
    if (tid < 32)  sb[tid] = db1[tid];
    if (tid < 2) { sc[tid] = mu_b[tid]; sc[2 + tid] = var_b[tid]; }
    __syncthreads();
    bool write_heads = (out_size >= 8 * n);
    float2* out_mu = (float2*)(out + 4 * n);
    float2* out_lv = (float2*)(out + 6 * n);
    int t = blockIdx.x * blockDim.x + tid;
    int stride = gridDim.x * blockDim.x;
    for (int i = t; i < n; i += stride) {
        float4 a = g_enc_acc[i];
        float inv = 1.0f / fmaxf(g_deg[i], 1.0f);
        float mu0 = a.x * inv + sc[0];
        float mu1 = a.y * inv + sc[1];
        float lv0 = a.z * inv + sc[2];
        float lv1 = a.w * inv + sc[3];
        float2 ep = eps[i];
        float z0 = mu0 + ep.x * expf(0.5f * lv0);
        float z1 = mu1 + ep.y * expf(0.5f * lv1);
        if (write_heads) {
            out_mu[i] = make_float2(mu0, mu1);
            out_lv[i] = make_float2(lv0, lv1);
        }
        float4 ra[8], rb[8];
        float* pa = (float*)ra;
        float* pb = (float*)rb;
#pragma unroll
        for (int k = 0; k < 32; k++) {
            const float* w = sw + k * 4;
            float b = w[2] * z0 + w[3] * z1;
            float aa = sb[k] + w[0] * z0 + w[1] * z1 - b;
            pa[k] = aa;
            pb[k] = b;
        }
#pragma unroll
        for (int q8 = 0; q8 < 8; q8++) {
            g_da[i * 8 + q8] = ra[q8];
            g_db[i * 8 + q8] = rb[q8];
        }
    }
}

// ---------------- finalize decoder output ----------------
__global__ void k_fin2(const float* __restrict__ b3, float4* __restrict__ out, int n) {
    int t = blockIdx.x * blockDim.x + threadIdx.x;
    int stride = gridDim.x * blockDim.x;
    float c0 = b3[0], c1 = b3[1], c2 = b3[2], c3 = b3[3];
    for (int i = t; i < n; i += stride) {
        float4 a = g_dec_acc[i];
        float d = g_deg[i];
        float4 o;
        if (d > 0.5f) {
            float inv = 1.0f / d;
            o = make_float4(a.x * inv + c0, a.y * inv + c1, a.z * inv + c2, a.w * inv + c3);
        } else {
            o = make_float4(0.f, 0.f, 0.f, 0.f);
        }
        out[i] = o;
    }
}

// ---------------- launch ----------------
extern "C" void kernel_launch(void* const* d_in, const int* in_sizes, int n_in,
                              void* d_out, int out_size) {
    const float* x     = (const float*)d_in[0];
    const float* eps   = (const float*)d_in[1];
    const float* gamma = (const float*)d_in[2];
    const float* beta  = (const float*)d_in[3];
    const float* ew1   = (const float*)d_in[4];
    const float* eb1   = (const float*)d_in[5];
    const float* ew2   = (const float*)d_in[6];
    const float* eb2   = (const float*)d_in[7];
    const float* muw   = (const float*)d_in[8];
    const float* mub   = (const float*)d_in[9];
    const float* vw    = (const float*)d_in[10];
    const float* vb    = (const float*)d_in[11];
    const float* dw1   = (const float*)d_in[12];
    const float* db1   = (const float*)d_in[13];
    const float* dw2   = (const float*)d_in[14];
    const float* db2   = (const float*)d_in[15];
    const float* dw3   = (const float*)d_in[16];
    const float* db3   = (const float*)d_in[17];
    const int*   ei    = (const int*)d_in[18];   // int32

    int n = in_sizes[0] / 4;
    int E = in_sizes[18] / 2;
    float* out = (float*)d_out;

    k_zero<<<256, 256>>>(n);
    k_bn_reduce<<<160, 256>>>((const float4*)x, n);
    k_prep_enc<<<256, 256>>>((const float4*)x, ew1, eb1, gamma, beta, n);

    int eblocks = 1480;   // grid-stride over 25000 tiles of 128 edges
    k_edge<0><<<eblocks, 128>>>(ei, E, n, ew2, eb2, muw, vw);
    k_fin1<<<256, 256>>>((const float2*)eps, mub, vb, dw1, db1, out, n, out_size);
    k_edge<1><<<eblocks, 128>>>(ei, E, n, dw2, db2, dw3, dw3 + 64);
    k_fin2<<<128, 256>>>(db3, (float4*)out, n);
}

// round 8
// speedup vs baseline: 2.8344x; 1.0701x over previous
#include <cuda_runtime.h>
#include <cstdint>

#define MAXN 100000
typedef unsigned long long ull;

// ---------------- device scratch (static: no allocations allowed) ----------------
__device__ float  g_bn[8];              // sum[4], sumsq[4]
__device__ float  g_deg[MAXN];
__device__ float4 g_enc_acc[MAXN];      // {mu0,mu1,lv0,lv1} sums
__device__ float4 g_dec_acc[MAXN];      // {o0..o3} sums
__device__ float4 g_ea[MAXN * 8];       // A@xn + b1  (N x 32)
__device__ float4 g_eb[MAXN * 8];       // B@xn       (N x 32)
__device__ float4 g_da[MAXN * 8];       // decoder A@z + b1
__device__ float4 g_db[MAXN * 8];       // decoder B@z

__device__ __forceinline__ void red_add_v4(float* p, float a, float b, float c, float d) {
    asm volatile("red.global.add.v4.f32 [%0], {%1,%2,%3,%4};"
                 :: "l"(p), "f"(a), "f"(b), "f"(c), "f"(d) : "memory");
}
__device__ __forceinline__ void red_add_f32(float* p, float a) {
    asm volatile("red.global.add.f32 [%0], %1;" :: "l"(p), "f"(a) : "memory");
}
__device__ __forceinline__ ull pack2(float lo, float hi) {
    ull d;
    asm("mov.b64 %0, {%1, %2};" : "=l"(d) : "f"(lo), "f"(hi));
    return d;
}
__device__ __forceinline__ ull packdup(float x) {
    ull d;
    asm("mov.b64 %0, {%1, %1};" : "=l"(d) : "f"(x));
    return d;
}
__device__ __forceinline__ void unpack2(ull v, float& lo, float& hi) {
    asm("mov.b64 {%0, %1}, %2;" : "=f"(lo), "=f"(hi) : "l"(v));
}
__device__ __forceinline__ ull fma2(ull a, ull b, ull c) {
    ull d;
    asm("fma.rn.f32x2 %0, %1, %2, %3;" : "=l"(d) : "l"(a), "l"(b), "l"(c));
    return d;
}
__device__ __forceinline__ uint32_t f2tf32(float f) {
    uint32_t r;
    asm("cvt.rna.tf32.f32 %0, %1;" : "=r"(r) : "f"(f));
    return r;
}

// ---------------- zero accumulators ----------------
__global__ void k_zero(int n) {
    int t = blockIdx.x * blockDim.x + threadIdx.x;
    int stride = gridDim.x * blockDim.x;
    float4 z = make_float4(0.f, 0.f, 0.f, 0.f);
    for (int i = t; i < n; i += stride) {
        g_enc_acc[i] = z;
        g_dec_acc[i] = z;
        g_deg[i] = 0.f;
    }
    if (t < 8) g_bn[t] = 0.f;
}

// ---------------- batchnorm statistics ----------------
__global__ void k_bn_reduce(const float4* __restrict__ x, int n) {
    int t = blockIdx.x * blockDim.x + threadIdx.x;
    int stride = gridDim.x * blockDim.x;
    float s[4] = {0.f, 0.f, 0.f, 0.f};
    float q[4] = {0.f, 0.f, 0.f, 0.f};
    for (int i = t; i < n; i += stride) {
        float4 v = x[i];
        s[0] += v.x; q[0] += v.x * v.x;
        s[1] += v.y; q[1] += v.y * v.y;
        s[2] += v.z; q[2] += v.z * v.z;
        s[3] += v.w; q[3] += v.w * v.w;
    }
#pragma unroll
    for (int o = 16; o > 0; o >>= 1) {
#pragma unroll
        for (int c = 0; c < 4; c++) {
            s[c] += __shfl_down_sync(0xffffffffu, s[c], o);
            q[c] += __shfl_down_sync(0xffffffffu, q[c], o);
        }
    }
    if ((threadIdx.x & 31) == 0) {
#pragma unroll
        for (int c = 0; c < 4; c++) {
            atomicAdd(&g_bn[c], s[c]);
            atomicAdd(&g_bn[4 + c], q[c]);
        }
    }
}

// ---------------- encoder node precompute: BN + linearized layer 1 ----------------
__global__ void k_prep_enc(const float4* __restrict__ x,
                           const float* __restrict__ w1, const float* __restrict__ b1,
                           const float* __restrict__ gamma, const float* __restrict__ beta,
                           int n) {
    __shared__ float sw[256];   // enc_w1 (32 x 8) row-major
    __shared__ float sb1[32];
    __shared__ float sm[4], ss[4], sbt[4];
    int tid = threadIdx.x;
    if (tid < 256) sw[tid] = w1[tid];
    if (tid < 32)  sb1[tid] = b1[tid];
    if (tid < 4) {
        float m = g_bn[tid] / (float)n;
        float var = g_bn[4 + tid] / (float)n - m * m;
        sm[tid]  = m;
        ss[tid]  = rsqrtf(var + 1e-5f) * gamma[tid];
        sbt[tid] = beta[tid];
    }
    __syncthreads();
    int t = blockIdx.x * blockDim.x + tid;
    int stride = gridDim.x * blockDim.x;
    for (int i = t; i < n; i += stride) {
        float4 xv = x[i];
        float x0 = (xv.x - sm[0]) * ss[0] + sbt[0];
        float x1 = (xv.y - sm[1]) * ss[1] + sbt[1];
        float x2 = (xv.z - sm[2]) * ss[2] + sbt[2];
        float x3 = (xv.w - sm[3]) * ss[3] + sbt[3];
        float4 ra[8], rb[8];
        float* pa = (float*)ra;
        float* pb = (float*)rb;
#pragma unroll
        for (int k = 0; k < 32; k++) {
            const float* w = sw + k * 8;
            float b = w[4] * x0 + w[5] * x1 + w[6] * x2 + w[7] * x3;
            float a = sb1[k] + w[0] * x0 + w[1] * x1 + w[2] * x2 + w[3] * x3 - b;
            pa[k] = a;
            pb[k] = b;
        }
#pragma unroll
        for (int q8 = 0; q8 < 8; q8++) {
            g_ea[i * 8 + q8] = ra[q8];
            g_eb[i * 8 + q8] = rb[q8];
        }
    }
}

// ---------------- per-edge kernel: staged gather -> mma.sync tf32 -> project + RED ----
// Warp-tile = 32 edges (M=32). A = tf32 u rows [32x32] in warp-private smem stage;
// B = W2 [32x32] as persistent register fragments. Bias seeds MMA accumulators.
// Proj coeffs in shared (broadcast LDS.64). Epilogue: relu, project, shfl-reduce, RED.
#define RS 36
template <int PHASE>
__global__ void __launch_bounds__(128, 4)
k_edge(const int* __restrict__ ei, int E, int n,
       const float* __restrict__ w2, const float* __restrict__ b2,
       const float* __restrict__ pA, const float* __restrict__ pB) {
    __shared__ __align__(16) float su[4 * 32 * RS];
    __shared__ ull s_pc01[32], s_pc23[32];   // {pA[c],pA[32+c]}, {pB[c],pB[32+c]}
    __shared__ float s_b2[32];
    int tid = threadIdx.x;
    int warp = tid >> 5, lane = tid & 31;
    int g = lane >> 2, tg = lane & 3;

    if (tid < 32) {
        s_pc01[tid] = pack2(pA[tid], pA[32 + tid]);
        s_pc23[tid] = pack2(pB[tid], pB[32 + tid]);
        s_b2[tid] = b2[tid];
    }

    // Persistent B fragments: bf0/bf1[nt][kt] = w2[8nt+g][8kt+tg(+4)]
    uint32_t bf0[4][4], bf1[4][4];
#pragma unroll
    for (int nt = 0; nt < 4; nt++)
#pragma unroll
        for (int kt = 0; kt < 4; kt++) {
            bf0[nt][kt] = f2tf32(w2[(8 * nt + g) * 32 + 8 * kt + tg]);
            bf1[nt][kt] = f2tf32(w2[(8 * nt + g) * 32 + 8 * kt + tg + 4]);
        }
    __syncthreads();

    const float4* fa = (PHASE == 0) ? g_ea : g_da;
    const float4* fb = (PHASE == 0) ? g_eb : g_db;
    float* acc = (PHASE == 0) ? (float*)g_enc_acc : (float*)g_dec_acc;

    float* stage = su + warp * 32 * RS;
    int c8 = lane & 7, rsub = lane >> 3;
    int ntiles = (E + 127) >> 7;
    const ull ONE = packdup(1.0f);

    for (int t = blockIdx.x; t < ntiles; t += gridDim.x) {
        int e = (t << 7) + (warp << 5) + lane;
        bool ok = (e < E);
        int ec = ok ? e : (E - 1);
        unsigned j = (unsigned)ei[ec];
        unsigned i = (unsigned)ei[E + ec];
        ok = ok && (j < (unsigned)n) && (i < (unsigned)n);
        unsigned js = ok ? j : 0u, is = ok ? i : 0u;
        unsigned oki = ok ? 1u : 0u;

        __syncwarp();   // stage is warp-private; prior iter reads done
#pragma unroll
        for (int gg = 0; gg < 8; gg++) {
            int er = 4 * gg + rsub;
            unsigned nd = __shfl_sync(0xffffffffu, is, er);
            unsigned ns = __shfl_sync(0xffffffffu, js, er);
            float4 a = fa[nd * 8 + c8];
            float4 b = fb[ns * 8 + c8];
            uint4 u;   // tf32 bit patterns (cvt overlaps gather latency)
            u.x = f2tf32(fmaxf(a.x + b.x, 0.f));
            u.y = f2tf32(fmaxf(a.y + b.y, 0.f));
            u.z = f2tf32(fmaxf(a.z + b.z, 0.f));
            u.w = f2tf32(fmaxf(a.w + b.w, 0.f));
            *(uint4*)(stage + er * RS + c8 * 4) = u;
        }
        __syncwarp();

#pragma unroll
        for (int mt = 0; mt < 2; mt++) {
            float c[4][4];
#pragma unroll
            for (int nt = 0; nt < 4; nt++) {
                float bb0 = s_b2[8 * nt + 2 * tg];
                float bb1 = s_b2[8 * nt + 2 * tg + 1];
                c[nt][0] = bb0; c[nt][1] = bb1;
                c[nt][2] = bb0; c[nt][3] = bb1;
            }

#pragma unroll
            for (int kt = 0; kt < 4; kt++) {
                const float* ab = stage + (mt * 16 + g) * RS + kt * 8 + tg;
                uint32_t a0 = __float_as_uint(ab[0]);
                uint32_t a1 = __float_as_uint(ab[8 * RS]);
                uint32_t a2 = __float_as_uint(ab[4]);
                uint32_t a3 = __float_as_uint(ab[8 * RS + 4]);
#pragma unroll
                for (int nt = 0; nt < 4; nt++) {
                    asm volatile(
                        "mma.sync.aligned.m16n8k8.row.col.f32.tf32.tf32.f32 "
                        "{%0,%1,%2,%3}, {%4,%5,%6,%7}, {%8,%9}, {%0,%1,%2,%3};"
                        : "+f"(c[nt][0]), "+f"(c[nt][1]), "+f"(c[nt][2]), "+f"(c[nt][3])
                        : "r"(a0), "r"(a1), "r"(a2), "r"(a3),
                          "r"(bf0[nt][kt]), "r"(bf1[nt][kt]));
                }
            }

            // epilogue: rows r0 = mt*16+g, r1 = mt*16+8+g
            ull p01a = 0, p23a = 0, p01b = 0, p23b = 0;
#pragma unroll
            for (int nt = 0; nt < 4; nt++) {
                int c0i = 8 * nt + 2 * tg;
                ull q0 = s_pc01[c0i], q1 = s_pc01[c0i + 1];
                ull q2 = s_pc23[c0i], q3 = s_pc23[c0i + 1];
                float r0 = fmaxf(c[nt][0], 0.f);
                float r1 = fmaxf(c[nt][1], 0.f);
                float r2 = fmaxf(c[nt][2], 0.f);
                float r3 = fmaxf(c[nt][3], 0.f);
                p01a = fma2(q0, packdup(r0), p01a);
                p23a = fma2(q2, packdup(r0), p23a);
                p01a = fma2(q1, packdup(r1), p01a);
                p23a = fma2(q3, packdup(r1), p23a);
                p01b = fma2(q0, packdup(r2), p01b);
                p23b = fma2(q2, packdup(r2), p23b);
                p01b = fma2(q1, packdup(r3), p01b);
                p23b = fma2(q3, packdup(r3), p23b);
            }
            // reduce over tg (lanes xor 1, xor 2)
#pragma unroll
            for (int m = 1; m <= 2; m <<= 1) {
                p01a = fma2(ONE, __shfl_xor_sync(0xffffffffu, p01a, m), p01a);
                p23a = fma2(ONE, __shfl_xor_sync(0xffffffffu, p23a, m), p23a);
                p01b = fma2(ONE, __shfl_xor_sync(0xffffffffu, p01b, m), p01b);
                p23b = fma2(ONE, __shfl_xor_sync(0xffffffffu, p23b, m), p23b);
            }
            unsigned iR0  = __shfl_sync(0xffffffffu, is,  mt * 16 + g);
            unsigned okR0 = __shfl_sync(0xffffffffu, oki, mt * 16 + g);
            unsigned iR1  = __shfl_sync(0xffffffffu, is,  mt * 16 + 8 + g);
            unsigned okR1 = __shfl_sync(0xffffffffu, oki, mt * 16 + 8 + g);
            if (tg == 0) {
                float r0, r1, r2, r3;
                if (okR0) {
                    unpack2(p01a, r0, r1);
                    unpack2(p23a, r2, r3);
                    red_add_v4(acc + 4 * iR0, r0, r1, r2, r3);
                    if (PHASE == 0) red_add_f32(&g_deg[iR0], 1.0f);
                }
                if (okR1) {
                    unpack2(p01b, r0, r1);
                    unpack2(p23b, r2, r3);
                    red_add_v4(acc + 4 * iR1, r0, r1, r2, r3);
                    if (PHASE == 0) red_add_f32(&g_deg[iR1], 1.0f);
                }
            }
        }
    }
}

// ---------------- finalize encoder: mu/logvar, reparam z, decoder layer-1 precompute ----------------
__global__ void k_fin1(const float2* __restrict__ eps,
                       const float* __restrict__ mu_b, const float* __restrict__ var_b,
                       const float* __restrict__ dw1, const float* __restrict__ db1,
                       float* __restrict__ out, int n, int out_size) {
    __shared__ float sw[128];   // dec_w1 (32 x 4)
    __shared__ float sb[32];
    __shared__ float sc[4];
    int tid = threadIdx.x;
    if (tid < 128) sw[tid] = dw1[tid];
    if (tid < 32)  sb[tid] = db1[tid];
    if (tid < 2) { sc[tid] = mu_b[tid]; sc[2 + tid] = var_b[tid]; }
    __syncthreads();
    bool write_heads = (out_size >= 8 * n);
    float2* out_mu = (float2*)(out + 4 * n);
    float2* out_lv = (float2*)(out + 6 * n);
    int t = blockIdx.x * blockDim.x + tid;
    int stride = gridDim.x * blockDim.x;
    for (int i = t; i < n; i += stride) {
        float4 a = g_enc_acc[i];
        float inv = 1.0f / fmaxf(g_deg[i], 1.0f);
        float mu0 = a.x * inv + sc[0];
        float mu1 = a.y * inv + sc[1];
        float lv0 = a.z * inv + sc[2];
        float lv1 = a.w * inv + sc[3];
        float2 ep = eps[i];
        float z0 = mu0 + ep.x * expf(0.5f * lv0);
        float z1 = mu1 + ep.y * expf(0.5f * lv1);
        if (write_heads) {
            out_mu[i] = make_float2(mu0, mu1);
            out_lv[i] = make_float2(lv0, lv1);
        }
        float4 ra[8], rb[8];
        float* pa = (float*)ra;
        float* pb = (float*)rb;
#pragma unroll
        for (int k = 0; k < 32; k++) {
            const float* w = sw + k * 4;
            float b = w[2] * z0 + w[3] * z1;
            float aa = sb[k] + w[0] * z0 + w[1] * z1 - b;
            pa[k] = aa;
            pb[k] = b;
        }
#pragma unroll
        for (int q8 = 0; q8 < 8; q8++) {
            g_da[i * 8 + q8] = ra[q8];
            g_db[i * 8 + q8] = rb[q8];
        }
    }
}

// ---------------- finalize decoder output ----------------
__global__ void k_fin2(const float* __restrict__ b3, float4* __restrict__ out, int n) {
    int t = blockIdx.x * blockDim.x + threadIdx.x;
    int stride = gridDim.x * blockDim.x;
    float c0 = b3[0], c1 = b3[1], c2 = b3[2], c3 = b3[3];
    for (int i = t; i < n; i += stride) {
        float4 a = g_dec_acc[i];
        float d = g_deg[i];
        float4 o;
        if (d > 0.5f) {
            float inv = 1.0f / d;
            o = make_float4(a.x * inv + c0, a.y * inv + c1, a.z * inv + c2, a.w * inv + c3);
        } else {
            o = make_float4(0.f, 0.f, 0.f, 0.f);
        }
        out[i] = o;
    }
}

// ---------------- launch ----------------
extern "C" void kernel_launch(void* const* d_in, const int* in_sizes, int n_in,
                              void* d_out, int out_size) {
    const float* x     = (const float*)d_in[0];
    const float* eps   = (const float*)d_in[1];
    const float* gamma = (const float*)d_in[2];
    const float* beta  = (const float*)d_in[3];
    const float* ew1   = (const float*)d_in[4];
    const float* eb1   = (const float*)d_in[5];
    const float* ew2   = (const float*)d_in[6];
    const float* eb2   = (const float*)d_in[7];
    const float* muw   = (const float*)d_in[8];
    const float* mub   = (const float*)d_in[9];
    const float* vw    = (const float*)d_in[10];
    const float* vb    = (const float*)d_in[11];
    const float* dw1   = (const float*)d_in[12];
    const float* db1   = (const float*)d_in[13];
    const float* dw2   = (const float*)d_in[14];
    const float* db2   = (const float*)d_in[15];
    const float* dw3   = (const float*)d_in[16];
    const float* db3   = (const float*)d_in[17];
    const int*   ei    = (const int*)d_in[18];   // int32

    int n = in_sizes[0] / 4;
    int E = in_sizes[18] / 2;
    float* out = (float*)d_out;

    k_zero<<<256, 256>>>(n);
    k_bn_reduce<<<160, 256>>>((const float4*)x, n);
    k_prep_enc<<<256, 256>>>((const float4*)x, ew1, eb1, gamma, beta, n);

    int eblocks = 1480;   // grid-stride over 25000 tiles of 128 edges
    k_edge<0><<<eblocks, 128>>>(ei, E, n, ew2, eb2, muw, vw);
    k_fin1<<<256, 256>>>((const float2*)eps, mub, vb, dw1, db1, out, n, out_size);
    k_edge<1><<<eblocks, 128>>>(ei, E, n, dw2, db2, dw3, dw3 + 64);
    k_fin2<<<128, 256>>>(db3, (float4*)out, n);
}